// round 8
// baseline (speedup 1.0000x reference)
#include <cuda_runtime.h>
#include <cuda_bf16.h>
#include <cstdint>

// Problem constants
#define BB    4
#define SS    2048
#define DD    256
#define HH    8
#define DHH   32
#define DFF   512
#define NTOK  (BB*SS)          // 8192
#define EPS   1e-5f
// ATT_SCALE * log2(e) : softmax via ex2
#define ATT_SC2 0.25503540f

// smem row pitch in halves (80B): conflict-free ldmatrix
#define PITCH 40

// ---------------------------------------------------------------------------
// Scratch (device globals; no allocations allowed)
// ---------------------------------------------------------------------------
__device__ __nv_bfloat16 g_yb [NTOK * DD];        // LN output (bf16)
__device__ __nv_bfloat16 g_ctxb[NTOK * DD];       // attention ctx (bf16)
__device__ float         g_x1 [NTOK * DD];        // residual after attention
__device__ __nv_bfloat16 g_hb [NTOK * DFF];       // FFN hidden (bf16)
__device__ __nv_bfloat16 g_qb[BB*HH * SS * DHH];  // Q bf16 [bh][s][32]
__device__ __nv_bfloat16 g_kb[BB*HH * SS * DHH];
__device__ __nv_bfloat16 g_vb[BB*HH * SS * DHH];
__device__ __nv_bfloat16 g_wqkvb[3*DD * DD];      // bf16 weights
__device__ __nv_bfloat16 g_wprojb[DD * DD];
__device__ __nv_bfloat16 g_w1b[DFF * DD];
__device__ __nv_bfloat16 g_w2b[DD * DFF];

__device__ __forceinline__ uint32_t packbf(float lo, float hi) {
    __nv_bfloat162 t = __floats2bfloat162_rn(lo, hi);
    return *reinterpret_cast<uint32_t*>(&t);
}
__device__ __forceinline__ float ex2(float x) {
    float y;
    asm("ex2.approx.f32 %0, %1;" : "=f"(y) : "f"(x));
    return y;
}

// ---------------------------------------------------------------------------
// One-shot fp32 -> bf16 conversion of ALL weight matrices (single launch)
// ---------------------------------------------------------------------------
__global__ void f2bf_all(const float* __restrict__ s0, const float* __restrict__ s1,
                         const float* __restrict__ s2, const float* __restrict__ s3,
                         __nv_bfloat16* __restrict__ d0, __nv_bfloat16* __restrict__ d1,
                         __nv_bfloat16* __restrict__ d2, __nv_bfloat16* __restrict__ d3) {
    int i = blockIdx.x * 256 + threadIdx.x;     // 0..131071
    int idx = i * 4;
    const float* src; __nv_bfloat16* dst; int off;
    if (idx < 196608)      { src = s0; dst = d0; off = idx; }
    else if (idx < 262144) { src = s1; dst = d1; off = idx - 196608; }
    else if (idx < 393216) { src = s2; dst = d2; off = idx - 262144; }
    else                   { src = s3; dst = d3; off = idx - 393216; }
    float4 v = *(const float4*)(src + off);
    uint2 o;
    o.x = packbf(v.x, v.y);
    o.y = packbf(v.z, v.w);
    *(uint2*)(dst + off) = o;
}

// ---------------------------------------------------------------------------
// LayerNorm -> bf16: one WARP per row (8 rows per 256-thread block)
// ---------------------------------------------------------------------------
__device__ __forceinline__ float warp_sum(float v) {
    #pragma unroll
    for (int o = 16; o > 0; o >>= 1) v += __shfl_xor_sync(0xffffffffu, v, o);
    return v;
}

__global__ __launch_bounds__(256) void ln_kernel(const float* __restrict__ x,
                                                 const float* __restrict__ g,
                                                 const float* __restrict__ b,
                                                 __nv_bfloat16* __restrict__ y) {
    int row  = blockIdx.x * 8 + (threadIdx.x >> 5);
    int lane = threadIdx.x & 31;
    const float* xr = x + (size_t)row * DD + lane * 8;

    float4 v0 = *(const float4*)(xr);
    float4 v1 = *(const float4*)(xr + 4);
    float d[8] = {v0.x, v0.y, v0.z, v0.w, v1.x, v1.y, v1.z, v1.w};

    float s = d[0]+d[1]+d[2]+d[3]+d[4]+d[5]+d[6]+d[7];
    float mean = warp_sum(s) * (1.0f / DD);

    float ss = 0.f;
    #pragma unroll
    for (int j = 0; j < 8; j++) { d[j] -= mean; ss += d[j] * d[j]; }
    float var = warp_sum(ss) * (1.0f / DD);
    float r = rsqrtf(var + EPS);

    float4 g0 = *(const float4*)(g + lane * 8);
    float4 g1 = *(const float4*)(g + lane * 8 + 4);
    float4 b0 = *(const float4*)(b + lane * 8);
    float4 b1 = *(const float4*)(b + lane * 8 + 4);
    float gg[8] = {g0.x, g0.y, g0.z, g0.w, g1.x, g1.y, g1.z, g1.w};
    float bb2[8] = {b0.x, b0.y, b0.z, b0.w, b1.x, b1.y, b1.z, b1.w};

    float o[8];
    #pragma unroll
    for (int j = 0; j < 8; j++) o[j] = d[j] * r * gg[j] + bb2[j];

    uint4 pk;
    pk.x = packbf(o[0], o[1]);
    pk.y = packbf(o[2], o[3]);
    pk.z = packbf(o[4], o[5]);
    pk.w = packbf(o[6], o[7]);
    *(uint4*)&y[(size_t)row * DD + lane * 8] = pk;
}

// ---------------------------------------------------------------------------
// mma helpers
// ---------------------------------------------------------------------------
__device__ __forceinline__ void ldmx4(uint32_t& r0, uint32_t& r1,
                                      uint32_t& r2, uint32_t& r3, uint32_t a) {
    asm volatile("ldmatrix.sync.aligned.m8n8.x4.shared.b16 {%0,%1,%2,%3}, [%4];\n"
                 : "=r"(r0), "=r"(r1), "=r"(r2), "=r"(r3) : "r"(a));
}
__device__ __forceinline__ void ldmx4t(uint32_t& r0, uint32_t& r1,
                                       uint32_t& r2, uint32_t& r3, uint32_t a) {
    asm volatile("ldmatrix.sync.aligned.m8n8.x4.trans.shared.b16 {%0,%1,%2,%3}, [%4];\n"
                 : "=r"(r0), "=r"(r1), "=r"(r2), "=r"(r3) : "r"(a));
}
__device__ __forceinline__ void mma16816(float* c, const uint32_t* a, const uint32_t* b) {
    asm volatile("mma.sync.aligned.m16n8k16.row.col.f32.bf16.bf16.f32 "
                 "{%0,%1,%2,%3}, {%4,%5,%6,%7}, {%8,%9}, {%0,%1,%2,%3};\n"
                 : "+f"(c[0]), "+f"(c[1]), "+f"(c[2]), "+f"(c[3])
                 : "r"(a[0]), "r"(a[1]), "r"(a[2]), "r"(a[3]),
                   "r"(b[0]), "r"(b[1]));
}

// ---------------------------------------------------------------------------
// bf16 tensor-core NT GEMM: C[n,m] = sum_k A[n,k]*W[m,k] + bias[m] (+ extras)
// Tile: 128 tokens x 64 features, BK=32. 256 threads = 8 warps (4 x 2).
// Register-prefetch pipeline on A/B tiles.
// MODE: 1 = fp32 out + residual, 2 = silu -> bf16 out, 3 = bf16 qkv scatter
// ---------------------------------------------------------------------------
template<int MODE>
__global__ __launch_bounds__(256) void gemm_bf(
        const __nv_bfloat16* __restrict__ A,
        const __nv_bfloat16* __restrict__ W,
        const float* __restrict__ bias,
        const float* __restrict__ res,
        float* __restrict__ C,
        __nv_bfloat16* __restrict__ Ob,
        __nv_bfloat16* __restrict__ Kb,
        __nv_bfloat16* __restrict__ Vb,
        int M, int K) {
    __shared__ __nv_bfloat16 As[128 * PITCH];
    __shared__ __nv_bfloat16 Bs[64 * PITCH];

    int t = threadIdx.x, w = t >> 5, lane = t & 31;
    int wm = w >> 1;
    int wn = w & 1;
    int row0 = blockIdx.y * 128;
    int col0 = blockIdx.x * 64;

    uint32_t abase = (uint32_t)__cvta_generic_to_shared(As);
    uint32_t bbase = (uint32_t)__cvta_generic_to_shared(Bs);

    // load indices
    int ar0 = t >> 1, ac0 = (t & 1) * 2;        // A: 2 uint4 per thread (rows 0..127, 2x)
    int br  = t >> 2, bc  = t & 3;              // B: 1 uint4 per thread

    float c[2][4][4];
    #pragma unroll
    for (int i = 0; i < 2; i++)
        #pragma unroll
        for (int j = 0; j < 4; j++)
            #pragma unroll
            for (int k = 0; k < 4; k++) c[i][j][k] = 0.f;

    // prefetch first tile
    uint4 pa0 = *(const uint4*)&A[(size_t)(row0 + ar0) * K + ac0 * 8];
    uint4 pa1 = *(const uint4*)&A[(size_t)(row0 + ar0) * K + (ac0 + 1) * 8];
    uint4 pb  = *(const uint4*)&W[(size_t)(col0 + br) * K + bc * 8];

    for (int k0 = 0; k0 < K; k0 += 32) {
        *(uint4*)&As[ar0 * PITCH + ac0 * 8]       = pa0;
        *(uint4*)&As[ar0 * PITCH + (ac0 + 1) * 8] = pa1;
        *(uint4*)&Bs[br * PITCH + bc * 8]         = pb;
        __syncthreads();

        if (k0 + 32 < K) {
            pa0 = *(const uint4*)&A[(size_t)(row0 + ar0) * K + k0 + 32 + ac0 * 8];
            pa1 = *(const uint4*)&A[(size_t)(row0 + ar0) * K + k0 + 32 + (ac0 + 1) * 8];
            pb  = *(const uint4*)&W[(size_t)(col0 + br) * K + k0 + 32 + bc * 8];
        }

        uint32_t bf[2][2][4];
        #pragma unroll
        for (int nt = 0; nt < 2; nt++) {
            int nrow = wn * 32 + nt * 16 + (lane & 7) + ((lane >> 4) << 3);
            #pragma unroll
            for (int ks = 0; ks < 2; ks++) {
                uint32_t ad = bbase + (uint32_t)(nrow * PITCH + ks * 16 + (lane & 8)) * 2;
                ldmx4(bf[nt][ks][0], bf[nt][ks][1], bf[nt][ks][2], bf[nt][ks][3], ad);
            }
        }
        #pragma unroll
        for (int mt = 0; mt < 2; mt++) {
            int arow = wm * 32 + mt * 16 + (lane & 15);
            #pragma unroll
            for (int ks = 0; ks < 2; ks++) {
                uint32_t af[4];
                uint32_t ad = abase + (uint32_t)(arow * PITCH + ks * 16 + ((lane >> 4) << 3)) * 2;
                ldmx4(af[0], af[1], af[2], af[3], ad);
                #pragma unroll
                for (int nt = 0; nt < 2; nt++) {
                    mma16816(c[mt][2 * nt],     af, &bf[nt][ks][0]);
                    mma16816(c[mt][2 * nt + 1], af, &bf[nt][ks][2]);
                }
            }
        }
        __syncthreads();
    }

    #pragma unroll
    for (int mt = 0; mt < 2; mt++) {
        #pragma unroll
        for (int half = 0; half < 2; half++) {
            int row = row0 + wm * 32 + mt * 16 + (lane >> 2) + half * 8;
            #pragma unroll
            for (int n8 = 0; n8 < 4; n8++) {
                int col = col0 + wn * 32 + n8 * 8 + 2 * (lane & 3);
                float v0 = c[mt][n8][2 * half]     + bias[col];
                float v1 = c[mt][n8][2 * half + 1] + bias[col + 1];
                if (MODE == 1) {
                    const float2 r2 = *(const float2*)&res[(size_t)row * M + col];
                    float2 o; o.x = v0 + r2.x; o.y = v1 + r2.y;
                    *(float2*)&C[(size_t)row * M + col] = o;
                } else if (MODE == 2) {
                    v0 = v0 * (1.0f / (1.0f + __expf(-v0)));
                    v1 = v1 * (1.0f / (1.0f + __expf(-v1)));
                    *(__nv_bfloat162*)&Ob[(size_t)row * M + col] =
                        __floats2bfloat162_rn(v0, v1);
                } else {
                    int seg = col >> 8, rem = col & 255;
                    int h = rem >> 5, d = rem & 31;
                    int b = row >> 11, s = row & 2047;
                    __nv_bfloat16* dst = (seg == 0) ? Ob : (seg == 1) ? Kb : Vb;
                    *(__nv_bfloat162*)&dst[((size_t)(b * HH + h) * SS + s) * DHH + d] =
                        __floats2bfloat162_rn(v0, v1);
                }
            }
        }
    }
}

// ---------------------------------------------------------------------------
// Tensor-core flash attention (bf16 mma, fp32 accum, no-max softmax).
// grid (BH=32, S/128=16), block 256 (8 warps; warp owns 16 query rows).
// l computed via extra mma against constant all-ones B fragment.
// Register-prefetch pipeline on K/V tiles.
// ---------------------------------------------------------------------------
__global__ __launch_bounds__(256) void attn_mma(const __nv_bfloat16* __restrict__ Qb,
                                                const __nv_bfloat16* __restrict__ Kb,
                                                const __nv_bfloat16* __restrict__ Vb,
                                                __nv_bfloat16* __restrict__ ctx) {
    __shared__ __nv_bfloat16 Qs[128 * PITCH];
    __shared__ __nv_bfloat16 Ks[128 * PITCH];
    __shared__ __nv_bfloat16 Vs[128 * PITCH];

    int bh = blockIdx.x;
    int qt = blockIdx.y;
    int t = threadIdx.x, w = t >> 5, lane = t & 31;

    const __nv_bfloat16* qsrc = Qb + ((size_t)bh * SS + qt * 128) * DHH;
    const __nv_bfloat16* ksrc = Kb + (size_t)bh * SS * DHH;
    const __nv_bfloat16* vsrc = Vb + (size_t)bh * SS * DHH;

    #pragma unroll
    for (int i = t; i < 512; i += 256) {
        int r = i >> 2, s = i & 3;
        *(uint4*)&Qs[r * PITCH + s * 8] = *(const uint4*)&qsrc[r * 32 + s * 8];
    }
    __syncthreads();

    uint32_t qbase = (uint32_t)__cvta_generic_to_shared(Qs);
    uint32_t kbase = (uint32_t)__cvta_generic_to_shared(Ks);
    uint32_t vbase = (uint32_t)__cvta_generic_to_shared(Vs);

    uint32_t qa[2][4];
    {
        int row = w * 16 + (lane & 15);
        #pragma unroll
        for (int ks = 0; ks < 2; ks++) {
            uint32_t a = qbase + (uint32_t)(row * PITCH + ks * 16 + ((lane >> 4) << 3)) * 2;
            ldmx4(qa[ks][0], qa[ks][1], qa[ks][2], qa[ks][3], a);
        }
    }

    float O[4][4];
    #pragma unroll
    for (int i = 0; i < 4; i++)
        #pragma unroll
        for (int j = 0; j < 4; j++) O[i][j] = 0.f;
    float Oext[4] = {0.f, 0.f, 0.f, 0.f};
    const uint32_t onesb[2] = {0x3F803F80u, 0x3F803F80u};

    // prefetch indices: 2 uint4 per thread for K, 2 for V
    int lr = t >> 1, lc = (t & 1) * 2;
    uint4 pk0, pk1, pv0, pv1;
    pk0 = *(const uint4*)&ksrc[lr * 32 + lc * 8];
    pk1 = *(const uint4*)&ksrc[lr * 32 + (lc + 1) * 8];
    pv0 = *(const uint4*)&vsrc[lr * 32 + lc * 8];
    pv1 = *(const uint4*)&vsrc[lr * 32 + (lc + 1) * 8];

    for (int kt = 0; kt < SS; kt += 128) {
        *(uint4*)&Ks[lr * PITCH + lc * 8]       = pk0;
        *(uint4*)&Ks[lr * PITCH + (lc + 1) * 8] = pk1;
        *(uint4*)&Vs[lr * PITCH + lc * 8]       = pv0;
        *(uint4*)&Vs[lr * PITCH + (lc + 1) * 8] = pv1;
        __syncthreads();

        if (kt + 128 < SS) {
            pk0 = *(const uint4*)&ksrc[(kt + 128 + lr) * 32 + lc * 8];
            pk1 = *(const uint4*)&ksrc[(kt + 128 + lr) * 32 + (lc + 1) * 8];
            pv0 = *(const uint4*)&vsrc[(kt + 128 + lr) * 32 + lc * 8];
            pv1 = *(const uint4*)&vsrc[(kt + 128 + lr) * 32 + (lc + 1) * 8];
        }

        #pragma unroll
        for (int sub = 0; sub < 2; sub++) {
            int koff = sub * 64;

            // ---- S = Q K^T over 64 keys ----
            float c[8][4];
            #pragma unroll
            for (int p2 = 0; p2 < 4; p2++) {
                uint32_t b0[4], b1[4];
                int nrow = koff + p2 * 16 + (lane & 7) + ((lane >> 4) << 3);
                uint32_t a0 = kbase + (uint32_t)(nrow * PITCH + (lane & 8)) * 2;
                ldmx4(b0[0], b0[1], b0[2], b0[3], a0);
                uint32_t a1 = kbase + (uint32_t)(nrow * PITCH + 16 + (lane & 8)) * 2;
                ldmx4(b1[0], b1[1], b1[2], b1[3], a1);
                float* c0 = c[2 * p2];
                float* c1 = c[2 * p2 + 1];
                #pragma unroll
                for (int i = 0; i < 4; i++) { c0[i] = 0.f; c1[i] = 0.f; }
                mma16816(c0, qa[0], &b0[0]);
                mma16816(c0, qa[1], &b1[0]);
                mma16816(c1, qa[0], &b0[2]);
                mma16816(c1, qa[1], &b1[2]);
            }

            // ---- softmax: p = 2^(s * scale*log2e), pack P, l via ones-mma ----
            #pragma unroll
            for (int j = 0; j < 4; j++) {
                float* c0 = c[2 * j];
                float* c1 = c[2 * j + 1];
                uint32_t pa[4];
                float p00 = ex2(c0[0] * ATT_SC2);
                float p01 = ex2(c0[1] * ATT_SC2);
                float p02 = ex2(c0[2] * ATT_SC2);
                float p03 = ex2(c0[3] * ATT_SC2);
                float p10 = ex2(c1[0] * ATT_SC2);
                float p11 = ex2(c1[1] * ATT_SC2);
                float p12 = ex2(c1[2] * ATT_SC2);
                float p13 = ex2(c1[3] * ATT_SC2);
                pa[0] = packbf(p00, p01);
                pa[1] = packbf(p02, p03);
                pa[2] = packbf(p10, p11);
                pa[3] = packbf(p12, p13);

                // l accumulation on tensor pipe
                mma16816(Oext, pa, onesb);

                // ---- O += P V for this 16-key slab ----
                int vrow = koff + j * 16 + (lane & 15);
                uint32_t v0[4], v1[4];
                uint32_t va = vbase + (uint32_t)(vrow * PITCH + ((lane >> 4) << 3)) * 2;
                ldmx4t(v0[0], v0[1], v0[2], v0[3], va);
                uint32_t vb2 = vbase + (uint32_t)(vrow * PITCH + 16 + ((lane >> 4) << 3)) * 2;
                ldmx4t(v1[0], v1[1], v1[2], v1[3], vb2);
                mma16816(O[0], pa, &v0[0]);
                mma16816(O[1], pa, &v0[2]);
                mma16816(O[2], pa, &v1[0]);
                mma16816(O[3], pa, &v1[2]);
            }
        }
        __syncthreads();
    }

    // Oext[0] = l for row (lane>>2), Oext[2] = l for row (lane>>2)+8
    float inv0 = 1.0f / Oext[0], inv1 = 1.0f / Oext[2];

    int b = bh >> 3, h = bh & 7;
    int r0 = qt * 128 + w * 16 + (lane >> 2);
    size_t base = ((size_t)(b * SS) + r0) * DD + h * DHH;
    #pragma unroll
    for (int nt = 0; nt < 4; nt++) {
        int colo = nt * 8 + 2 * (lane & 3);
        *(__nv_bfloat162*)&ctx[base + colo] =
            __floats2bfloat162_rn(O[nt][0] * inv0, O[nt][1] * inv0);
        *(__nv_bfloat162*)&ctx[base + 8 * DD + colo] =
            __floats2bfloat162_rn(O[nt][2] * inv1, O[nt][3] * inv1);
    }
}

// ---------------------------------------------------------------------------
// Launch
// ---------------------------------------------------------------------------
extern "C" void kernel_launch(void* const* d_in, const int* in_sizes, int n_in,
                              void* d_out, int out_size) {
    const float* x      = (const float*)d_in[0];
    const float* ln1_g  = (const float*)d_in[1];
    const float* ln1_b  = (const float*)d_in[2];
    const float* w_qkv  = (const float*)d_in[3];
    const float* b_qkv  = (const float*)d_in[4];
    const float* w_proj = (const float*)d_in[5];
    const float* b_proj = (const float*)d_in[6];
    const float* ln2_g  = (const float*)d_in[7];
    const float* ln2_b  = (const float*)d_in[8];
    const float* w1     = (const float*)d_in[9];
    const float* b1     = (const float*)d_in[10];
    const float* w2     = (const float*)d_in[11];
    const float* b2     = (const float*)d_in[12];
    float* out = (float*)d_out;

    __nv_bfloat16 *yb, *ctxb, *hb, *qb, *kb, *vb, *wqkvb, *wprojb, *w1b, *w2b;
    float *x1;
    cudaGetSymbolAddress((void**)&yb,     g_yb);
    cudaGetSymbolAddress((void**)&ctxb,   g_ctxb);
    cudaGetSymbolAddress((void**)&x1,     g_x1);
    cudaGetSymbolAddress((void**)&hb,     g_hb);
    cudaGetSymbolAddress((void**)&qb,     g_qb);
    cudaGetSymbolAddress((void**)&kb,     g_kb);
    cudaGetSymbolAddress((void**)&vb,     g_vb);
    cudaGetSymbolAddress((void**)&wqkvb,  g_wqkvb);
    cudaGetSymbolAddress((void**)&wprojb, g_wprojb);
    cudaGetSymbolAddress((void**)&w1b,    g_w1b);
    cudaGetSymbolAddress((void**)&w2b,    g_w2b);

    // 0. all weights fp32 -> bf16, one launch
    f2bf_all<<<512, 256>>>(w_qkv, w_proj, w1, w2, wqkvb, wprojb, w1b, w2b);

    // 1. LN1 -> bf16
    ln_kernel<<<NTOK/8, 256>>>(x, ln1_g, ln1_b, yb);
    // 2. QKV GEMM -> bf16 Q/K/V [bh][s][32]
    gemm_bf<3><<<dim3(768/64, NTOK/128), 256>>>(yb, wqkvb, b_qkv, nullptr, nullptr,
                                                qb, kb, vb, 3*DD, DD);
    // 3. attention -> ctx bf16
    attn_mma<<<dim3(BB*HH, SS/128), 256>>>(qb, kb, vb, ctxb);
    // 4. proj + residual -> x1 fp32
    gemm_bf<1><<<dim3(DD/64, NTOK/128), 256>>>(ctxb, wprojb, b_proj, x, x1,
                                               nullptr, nullptr, nullptr, DD, DD);
    // 5. LN2 -> bf16
    ln_kernel<<<NTOK/8, 256>>>(x1, ln2_g, ln2_b, yb);
    // 6. FFN1 + silu -> bf16 h
    gemm_bf<2><<<dim3(DFF/64, NTOK/128), 256>>>(yb, w1b, b1, nullptr, nullptr,
                                                hb, nullptr, nullptr, DFF, DD);
    // 7. FFN2 + residual -> out fp32
    gemm_bf<1><<<dim3(DD/64, NTOK/128), 256>>>(hb, w2b, b2, x1, out,
                                               nullptr, nullptr, nullptr, DD, DFF);
}

// round 9
// speedup vs baseline: 1.0950x; 1.0950x over previous
#include <cuda_runtime.h>
#include <cuda_bf16.h>
#include <cstdint>

// Problem constants
#define BB    4
#define SS    2048
#define DD    256
#define HH    8
#define DHH   32
#define DFF   512
#define NTOK  (BB*SS)          // 8192
#define EPS   1e-5f
// ATT_SCALE * log2(e) : softmax via ex2
#define ATT_SC2 0.25503540f

// smem row pitch in halves (80B): conflict-free + 16B-aligned rows for ldmatrix
#define PITCH 40

// ---------------------------------------------------------------------------
// Scratch (device globals; no allocations allowed)
// ---------------------------------------------------------------------------
__device__ __nv_bfloat16 g_yb [NTOK * DD];        // LN output (bf16)
__device__ __nv_bfloat16 g_ctxb[NTOK * DD];       // attention ctx (bf16)
__device__ float         g_x1 [NTOK * DD];        // residual after attention
__device__ __nv_bfloat16 g_hb [NTOK * DFF];       // FFN hidden (bf16)
__device__ __nv_bfloat16 g_qb[BB*HH * SS * DHH];  // Q bf16 [bh][s][32]
__device__ __nv_bfloat16 g_kb[BB*HH * SS * DHH];
__device__ __nv_bfloat16 g_vb[BB*HH * SS * DHH];
__device__ __nv_bfloat16 g_wqkvb[3*DD * DD];      // bf16 weights
__device__ __nv_bfloat16 g_wprojb[DD * DD];
__device__ __nv_bfloat16 g_w1b[DFF * DD];
__device__ __nv_bfloat16 g_w2b[DD * DFF];

__device__ __forceinline__ uint32_t packbf(float lo, float hi) {
    __nv_bfloat162 t = __floats2bfloat162_rn(lo, hi);
    return *reinterpret_cast<uint32_t*>(&t);
}
__device__ __forceinline__ float ex2(float x) {
    float y;
    asm("ex2.approx.f32 %0, %1;" : "=f"(y) : "f"(x));
    return y;
}
__device__ __forceinline__ void cpa16(uint32_t dst, const void* src) {
    asm volatile("cp.async.cg.shared.global [%0], [%1], 16;" :: "r"(dst), "l"(src));
}

// ---------------------------------------------------------------------------
// One-shot fp32 -> bf16 conversion of ALL weight matrices (single launch)
// ---------------------------------------------------------------------------
__global__ void f2bf_all(const float* __restrict__ s0, const float* __restrict__ s1,
                         const float* __restrict__ s2, const float* __restrict__ s3,
                         __nv_bfloat16* __restrict__ d0, __nv_bfloat16* __restrict__ d1,
                         __nv_bfloat16* __restrict__ d2, __nv_bfloat16* __restrict__ d3) {
    int i = blockIdx.x * 256 + threadIdx.x;     // 0..131071
    int idx = i * 4;
    const float* src; __nv_bfloat16* dst; int off;
    if (idx < 196608)      { src = s0; dst = d0; off = idx; }
    else if (idx < 262144) { src = s1; dst = d1; off = idx - 196608; }
    else if (idx < 393216) { src = s2; dst = d2; off = idx - 262144; }
    else                   { src = s3; dst = d3; off = idx - 393216; }
    float4 v = *(const float4*)(src + off);
    uint2 o;
    o.x = packbf(v.x, v.y);
    o.y = packbf(v.z, v.w);
    *(uint2*)(dst + off) = o;
}

// ---------------------------------------------------------------------------
// LayerNorm -> bf16: one WARP per row (8 rows per 256-thread block)
// ---------------------------------------------------------------------------
__device__ __forceinline__ float warp_sum(float v) {
    #pragma unroll
    for (int o = 16; o > 0; o >>= 1) v += __shfl_xor_sync(0xffffffffu, v, o);
    return v;
}

__global__ __launch_bounds__(256) void ln_kernel(const float* __restrict__ x,
                                                 const float* __restrict__ g,
                                                 const float* __restrict__ b,
                                                 __nv_bfloat16* __restrict__ y) {
    int row  = blockIdx.x * 8 + (threadIdx.x >> 5);
    int lane = threadIdx.x & 31;
    const float* xr = x + (size_t)row * DD + lane * 8;

    float4 v0 = *(const float4*)(xr);
    float4 v1 = *(const float4*)(xr + 4);
    float d[8] = {v0.x, v0.y, v0.z, v0.w, v1.x, v1.y, v1.z, v1.w};

    float s = d[0]+d[1]+d[2]+d[3]+d[4]+d[5]+d[6]+d[7];
    float mean = warp_sum(s) * (1.0f / DD);

    float ss = 0.f;
    #pragma unroll
    for (int j = 0; j < 8; j++) { d[j] -= mean; ss += d[j] * d[j]; }
    float var = warp_sum(ss) * (1.0f / DD);
    float r = rsqrtf(var + EPS);

    float4 g0 = *(const float4*)(g + lane * 8);
    float4 g1 = *(const float4*)(g + lane * 8 + 4);
    float4 b0 = *(const float4*)(b + lane * 8);
    float4 b1 = *(const float4*)(b + lane * 8 + 4);
    float gg[8] = {g0.x, g0.y, g0.z, g0.w, g1.x, g1.y, g1.z, g1.w};
    float bb2[8] = {b0.x, b0.y, b0.z, b0.w, b1.x, b1.y, b1.z, b1.w};

    float o[8];
    #pragma unroll
    for (int j = 0; j < 8; j++) o[j] = d[j] * r * gg[j] + bb2[j];

    uint4 pk;
    pk.x = packbf(o[0], o[1]);
    pk.y = packbf(o[2], o[3]);
    pk.z = packbf(o[4], o[5]);
    pk.w = packbf(o[6], o[7]);
    *(uint4*)&y[(size_t)row * DD + lane * 8] = pk;
}

// ---------------------------------------------------------------------------
// mma helpers
// ---------------------------------------------------------------------------
__device__ __forceinline__ void ldmx4(uint32_t& r0, uint32_t& r1,
                                      uint32_t& r2, uint32_t& r3, uint32_t a) {
    asm volatile("ldmatrix.sync.aligned.m8n8.x4.shared.b16 {%0,%1,%2,%3}, [%4];\n"
                 : "=r"(r0), "=r"(r1), "=r"(r2), "=r"(r3) : "r"(a));
}
__device__ __forceinline__ void ldmx4t(uint32_t& r0, uint32_t& r1,
                                       uint32_t& r2, uint32_t& r3, uint32_t a) {
    asm volatile("ldmatrix.sync.aligned.m8n8.x4.trans.shared.b16 {%0,%1,%2,%3}, [%4];\n"
                 : "=r"(r0), "=r"(r1), "=r"(r2), "=r"(r3) : "r"(a));
}
__device__ __forceinline__ void mma16816(float* c, const uint32_t* a, const uint32_t* b) {
    asm volatile("mma.sync.aligned.m16n8k16.row.col.f32.bf16.bf16.f32 "
                 "{%0,%1,%2,%3}, {%4,%5,%6,%7}, {%8,%9}, {%0,%1,%2,%3};\n"
                 : "+f"(c[0]), "+f"(c[1]), "+f"(c[2]), "+f"(c[3])
                 : "r"(a[0]), "r"(a[1]), "r"(a[2]), "r"(a[3]),
                   "r"(b[0]), "r"(b[1]));
}

// ---------------------------------------------------------------------------
// bf16 tensor-core NT GEMM (R6 version, no prefetch):
// C[n,m] = sum_k A[n,k]*W[m,k] + bias[m] (+ extras)
// Tile: 128 tokens x 64 features, BK=32. 256 threads = 8 warps (4 x 2).
// MODE: 1 = fp32 out + residual, 2 = silu -> bf16 out, 3 = bf16 qkv scatter
// ---------------------------------------------------------------------------
template<int MODE>
__global__ __launch_bounds__(256) void gemm_bf(
        const __nv_bfloat16* __restrict__ A,
        const __nv_bfloat16* __restrict__ W,
        const float* __restrict__ bias,
        const float* __restrict__ res,
        float* __restrict__ C,
        __nv_bfloat16* __restrict__ Ob,
        __nv_bfloat16* __restrict__ Kb,
        __nv_bfloat16* __restrict__ Vb,
        int M, int K) {
    __shared__ __nv_bfloat16 As[128 * PITCH];
    __shared__ __nv_bfloat16 Bs[64 * PITCH];

    int t = threadIdx.x, w = t >> 5, lane = t & 31;
    int wm = w >> 1;
    int wn = w & 1;
    int row0 = blockIdx.y * 128;
    int col0 = blockIdx.x * 64;

    uint32_t abase = (uint32_t)__cvta_generic_to_shared(As);
    uint32_t bbase = (uint32_t)__cvta_generic_to_shared(Bs);

    float c[2][4][4];
    #pragma unroll
    for (int i = 0; i < 2; i++)
        #pragma unroll
        for (int j = 0; j < 4; j++)
            #pragma unroll
            for (int k = 0; k < 4; k++) c[i][j][k] = 0.f;

    for (int k0 = 0; k0 < K; k0 += 32) {
        #pragma unroll
        for (int i = t; i < 512; i += 256) {
            int r = i >> 2, cc = i & 3;
            *(uint4*)&As[r * PITCH + cc * 8] =
                *(const uint4*)&A[(size_t)(row0 + r) * K + k0 + cc * 8];
        }
        {
            int r = t >> 2, cc = t & 3;
            *(uint4*)&Bs[r * PITCH + cc * 8] =
                *(const uint4*)&W[(size_t)(col0 + r) * K + k0 + cc * 8];
        }
        __syncthreads();

        uint32_t bf[2][2][4];
        #pragma unroll
        for (int nt = 0; nt < 2; nt++) {
            int nrow = wn * 32 + nt * 16 + (lane & 7) + ((lane >> 4) << 3);
            #pragma unroll
            for (int ks = 0; ks < 2; ks++) {
                uint32_t ad = bbase + (uint32_t)(nrow * PITCH + ks * 16 + (lane & 8)) * 2;
                ldmx4(bf[nt][ks][0], bf[nt][ks][1], bf[nt][ks][2], bf[nt][ks][3], ad);
            }
        }
        #pragma unroll
        for (int mt = 0; mt < 2; mt++) {
            int arow = wm * 32 + mt * 16 + (lane & 15);
            #pragma unroll
            for (int ks = 0; ks < 2; ks++) {
                uint32_t af[4];
                uint32_t ad = abase + (uint32_t)(arow * PITCH + ks * 16 + ((lane >> 4) << 3)) * 2;
                ldmx4(af[0], af[1], af[2], af[3], ad);
                #pragma unroll
                for (int nt = 0; nt < 2; nt++) {
                    mma16816(c[mt][2 * nt],     af, &bf[nt][ks][0]);
                    mma16816(c[mt][2 * nt + 1], af, &bf[nt][ks][2]);
                }
            }
        }
        __syncthreads();
    }

    #pragma unroll
    for (int mt = 0; mt < 2; mt++) {
        #pragma unroll
        for (int half = 0; half < 2; half++) {
            int row = row0 + wm * 32 + mt * 16 + (lane >> 2) + half * 8;
            #pragma unroll
            for (int n8 = 0; n8 < 4; n8++) {
                int col = col0 + wn * 32 + n8 * 8 + 2 * (lane & 3);
                float v0 = c[mt][n8][2 * half]     + bias[col];
                float v1 = c[mt][n8][2 * half + 1] + bias[col + 1];
                if (MODE == 1) {
                    const float2 r2 = *(const float2*)&res[(size_t)row * M + col];
                    float2 o; o.x = v0 + r2.x; o.y = v1 + r2.y;
                    *(float2*)&C[(size_t)row * M + col] = o;
                } else if (MODE == 2) {
                    v0 = v0 * (1.0f / (1.0f + __expf(-v0)));
                    v1 = v1 * (1.0f / (1.0f + __expf(-v1)));
                    *(__nv_bfloat162*)&Ob[(size_t)row * M + col] =
                        __floats2bfloat162_rn(v0, v1);
                } else {
                    int seg = col >> 8, rem = col & 255;
                    int h = rem >> 5, d = rem & 31;
                    int b = row >> 11, s = row & 2047;
                    __nv_bfloat16* dst = (seg == 0) ? Ob : (seg == 1) ? Kb : Vb;
                    *(__nv_bfloat162*)&dst[((size_t)(b * HH + h) * SS + s) * DHH + d] =
                        __floats2bfloat162_rn(v0, v1);
                }
            }
        }
    }
}

// ---------------------------------------------------------------------------
// Tensor-core flash attention (bf16 mma, fp32 accum, no-max softmax).
// grid (BH=32, S/128=16), block 128 (4 warps; warp owns 32 query rows).
// K/V: 64-key tiles, cp.async double-buffered. K/V fragments reused across
// the warp's two 16-row m-tiles (halves LDSM traffic vs 16-row warps).
// l computed via extra mma against constant all-ones B fragment.
// ---------------------------------------------------------------------------
__global__ __launch_bounds__(128) void attn_mma(const __nv_bfloat16* __restrict__ Qb,
                                                const __nv_bfloat16* __restrict__ Kb,
                                                const __nv_bfloat16* __restrict__ Vb,
                                                __nv_bfloat16* __restrict__ ctx) {
    __shared__ __nv_bfloat16 Qs[128 * PITCH];
    __shared__ __nv_bfloat16 Ks[2][64 * PITCH];
    __shared__ __nv_bfloat16 Vs[2][64 * PITCH];

    int bh = blockIdx.x;
    int qt = blockIdx.y;
    int t = threadIdx.x, w = t >> 5, lane = t & 31;

    const __nv_bfloat16* qsrc = Qb + ((size_t)bh * SS + qt * 128) * DHH;
    const __nv_bfloat16* ksrc = Kb + (size_t)bh * SS * DHH;
    const __nv_bfloat16* vsrc = Vb + (size_t)bh * SS * DHH;

    uint32_t qbase = (uint32_t)__cvta_generic_to_shared(Qs);
    uint32_t kb_[2] = { (uint32_t)__cvta_generic_to_shared(Ks[0]),
                        (uint32_t)__cvta_generic_to_shared(Ks[1]) };
    uint32_t vb_[2] = { (uint32_t)__cvta_generic_to_shared(Vs[0]),
                        (uint32_t)__cvta_generic_to_shared(Vs[1]) };

    // Q tile: 128 rows x 32 halves = 512 uint4, 4 per thread
    #pragma unroll
    for (int i = t; i < 512; i += 128) {
        int r = i >> 2, s = i & 3;
        *(uint4*)&Qs[r * PITCH + s * 8] = *(const uint4*)&qsrc[r * 32 + s * 8];
    }

    // cp.async per thread per tile: rows (t>>2) and (t>>2)+32, col group t&3
    int lr = t >> 2, ls = t & 3;
    uint32_t so0 = (uint32_t)(lr * PITCH + ls * 8) * 2;
    uint32_t so1 = (uint32_t)((lr + 32) * PITCH + ls * 8) * 2;

    // prologue: tile 0 into buffer 0
    cpa16(kb_[0] + so0, &ksrc[lr * 32 + ls * 8]);
    cpa16(kb_[0] + so1, &ksrc[(lr + 32) * 32 + ls * 8]);
    cpa16(vb_[0] + so0, &vsrc[lr * 32 + ls * 8]);
    cpa16(vb_[0] + so1, &vsrc[(lr + 32) * 32 + ls * 8]);
    asm volatile("cp.async.commit_group;");

    __syncthreads();   // Q ready

    // Q A-fragments: 2 m-tiles x 2 k-steps
    uint32_t qa[2][2][4];
    #pragma unroll
    for (int mt = 0; mt < 2; mt++) {
        int row = w * 32 + mt * 16 + (lane & 15);
        #pragma unroll
        for (int ks = 0; ks < 2; ks++) {
            uint32_t a = qbase + (uint32_t)(row * PITCH + ks * 16 + ((lane >> 4) << 3)) * 2;
            ldmx4(qa[mt][ks][0], qa[mt][ks][1], qa[mt][ks][2], qa[mt][ks][3], a);
        }
    }

    float O[2][4][4];
    #pragma unroll
    for (int mt = 0; mt < 2; mt++)
        #pragma unroll
        for (int i = 0; i < 4; i++)
            #pragma unroll
            for (int j = 0; j < 4; j++) O[mt][i][j] = 0.f;
    float Oext[2][4] = {{0.f,0.f,0.f,0.f},{0.f,0.f,0.f,0.f}};
    const uint32_t onesb[2] = {0x3F803F80u, 0x3F803F80u};

    const int NIT = SS / 64;   // 32
    for (int it = 0; it < NIT; it++) {
        int cur = it & 1;
        if (it + 1 < NIT) {
            int koff = (it + 1) * 64;
            int nb = cur ^ 1;
            cpa16(kb_[nb] + so0, &ksrc[(koff + lr) * 32 + ls * 8]);
            cpa16(kb_[nb] + so1, &ksrc[(koff + lr + 32) * 32 + ls * 8]);
            cpa16(vb_[nb] + so0, &vsrc[(koff + lr) * 32 + ls * 8]);
            cpa16(vb_[nb] + so1, &vsrc[(koff + lr + 32) * 32 + ls * 8]);
            asm volatile("cp.async.commit_group;");
            asm volatile("cp.async.wait_group 1;");
        } else {
            asm volatile("cp.async.wait_group 0;");
        }
        __syncthreads();

        uint32_t kba = kb_[cur], vba = vb_[cur];
        #pragma unroll
        for (int j = 0; j < 4; j++) {            // 16-key slabs
            // K fragments (shared across both m-tiles)
            uint32_t b0[4], b1[4];
            int nrow = j * 16 + (lane & 7) + ((lane >> 4) << 3);
            ldmx4(b0[0], b0[1], b0[2], b0[3],
                  kba + (uint32_t)(nrow * PITCH + (lane & 8)) * 2);
            ldmx4(b1[0], b1[1], b1[2], b1[3],
                  kba + (uint32_t)(nrow * PITCH + 16 + (lane & 8)) * 2);

            // S = Q K^T for both m-tiles
            float c[2][2][4];
            #pragma unroll
            for (int mt = 0; mt < 2; mt++) {
                #pragma unroll
                for (int i = 0; i < 4; i++) { c[mt][0][i] = 0.f; c[mt][1][i] = 0.f; }
                mma16816(c[mt][0], qa[mt][0], &b0[0]);
                mma16816(c[mt][0], qa[mt][1], &b1[0]);
                mma16816(c[mt][1], qa[mt][0], &b0[2]);
                mma16816(c[mt][1], qa[mt][1], &b1[2]);
            }

            // softmax + pack P + l via ones-mma
            uint32_t pa[2][4];
            #pragma unroll
            for (int mt = 0; mt < 2; mt++) {
                float p00 = ex2(c[mt][0][0] * ATT_SC2);
                float p01 = ex2(c[mt][0][1] * ATT_SC2);
                float p02 = ex2(c[mt][0][2] * ATT_SC2);
                float p03 = ex2(c[mt][0][3] * ATT_SC2);
                float p10 = ex2(c[mt][1][0] * ATT_SC2);
                float p11 = ex2(c[mt][1][1] * ATT_SC2);
                float p12 = ex2(c[mt][1][2] * ATT_SC2);
                float p13 = ex2(c[mt][1][3] * ATT_SC2);
                pa[mt][0] = packbf(p00, p01);
                pa[mt][1] = packbf(p02, p03);
                pa[mt][2] = packbf(p10, p11);
                pa[mt][3] = packbf(p12, p13);
                mma16816(Oext[mt], pa[mt], onesb);
            }

            // V fragments (shared across both m-tiles)
            int vrow = j * 16 + (lane & 15);
            uint32_t v0[4], v1[4];
            ldmx4t(v0[0], v0[1], v0[2], v0[3],
                   vba + (uint32_t)(vrow * PITCH + ((lane >> 4) << 3)) * 2);
            ldmx4t(v1[0], v1[1], v1[2], v1[3],
                   vba + (uint32_t)(vrow * PITCH + 16 + ((lane >> 4) << 3)) * 2);

            #pragma unroll
            for (int mt = 0; mt < 2; mt++) {
                mma16816(O[mt][0], pa[mt], &v0[0]);
                mma16816(O[mt][1], pa[mt], &v0[2]);
                mma16816(O[mt][2], pa[mt], &v1[0]);
                mma16816(O[mt][3], pa[mt], &v1[2]);
            }
        }
        __syncthreads();
    }

    // epilogue: Oext[mt][0] = l(row), Oext[mt][2] = l(row+8)
    int b = bh >> 3, h = bh & 7;
    #pragma unroll
    for (int mt = 0; mt < 2; mt++) {
        float inv0 = 1.0f / Oext[mt][0], inv1 = 1.0f / Oext[mt][2];
        int r0 = qt * 128 + w * 32 + mt * 16 + (lane >> 2);
        size_t base = ((size_t)(b * SS) + r0) * DD + h * DHH;
        #pragma unroll
        for (int nt = 0; nt < 4; nt++) {
            int colo = nt * 8 + 2 * (lane & 3);
            *(__nv_bfloat162*)&ctx[base + colo] =
                __floats2bfloat162_rn(O[mt][nt][0] * inv0, O[mt][nt][1] * inv0);
            *(__nv_bfloat162*)&ctx[base + 8 * DD + colo] =
                __floats2bfloat162_rn(O[mt][nt][2] * inv1, O[mt][nt][3] * inv1);
        }
    }
}

// ---------------------------------------------------------------------------
// Launch
// ---------------------------------------------------------------------------
extern "C" void kernel_launch(void* const* d_in, const int* in_sizes, int n_in,
                              void* d_out, int out_size) {
    const float* x      = (const float*)d_in[0];
    const float* ln1_g  = (const float*)d_in[1];
    const float* ln1_b  = (const float*)d_in[2];
    const float* w_qkv  = (const float*)d_in[3];
    const float* b_qkv  = (const float*)d_in[4];
    const float* w_proj = (const float*)d_in[5];
    const float* b_proj = (const float*)d_in[6];
    const float* ln2_g  = (const float*)d_in[7];
    const float* ln2_b  = (const float*)d_in[8];
    const float* w1     = (const float*)d_in[9];
    const float* b1     = (const float*)d_in[10];
    const float* w2     = (const float*)d_in[11];
    const float* b2     = (const float*)d_in[12];
    float* out = (float*)d_out;

    __nv_bfloat16 *yb, *ctxb, *hb, *qb, *kb, *vb, *wqkvb, *wprojb, *w1b, *w2b;
    float *x1;
    cudaGetSymbolAddress((void**)&yb,     g_yb);
    cudaGetSymbolAddress((void**)&ctxb,   g_ctxb);
    cudaGetSymbolAddress((void**)&x1,     g_x1);
    cudaGetSymbolAddress((void**)&hb,     g_hb);
    cudaGetSymbolAddress((void**)&qb,     g_qb);
    cudaGetSymbolAddress((void**)&kb,     g_kb);
    cudaGetSymbolAddress((void**)&vb,     g_vb);
    cudaGetSymbolAddress((void**)&wqkvb,  g_wqkvb);
    cudaGetSymbolAddress((void**)&wprojb, g_wprojb);
    cudaGetSymbolAddress((void**)&w1b,    g_w1b);
    cudaGetSymbolAddress((void**)&w2b,    g_w2b);

    // 0. all weights fp32 -> bf16, one launch
    f2bf_all<<<512, 256>>>(w_qkv, w_proj, w1, w2, wqkvb, wprojb, w1b, w2b);

    // 1. LN1 -> bf16
    ln_kernel<<<NTOK/8, 256>>>(x, ln1_g, ln1_b, yb);
    // 2. QKV GEMM -> bf16 Q/K/V [bh][s][32]
    gemm_bf<3><<<dim3(768/64, NTOK/128), 256>>>(yb, wqkvb, b_qkv, nullptr, nullptr,
                                                qb, kb, vb, 3*DD, DD);
    // 3. attention -> ctx bf16
    attn_mma<<<dim3(BB*HH, SS/128), 128>>>(qb, kb, vb, ctxb);
    // 4. proj + residual -> x1 fp32
    gemm_bf<1><<<dim3(DD/64, NTOK/128), 256>>>(ctxb, wprojb, b_proj, x, x1,
                                               nullptr, nullptr, nullptr, DD, DD);
    // 5. LN2 -> bf16
    ln_kernel<<<NTOK/8, 256>>>(x1, ln2_g, ln2_b, yb);
    // 6. FFN1 + silu -> bf16 h
    gemm_bf<2><<<dim3(DFF/64, NTOK/128), 256>>>(yb, w1b, b1, nullptr, nullptr,
                                                hb, nullptr, nullptr, DFF, DD);
    // 7. FFN2 + residual -> out fp32
    gemm_bf<1><<<dim3(DD/64, NTOK/128), 256>>>(hb, w2b, b2, x1, out,
                                               nullptr, nullptr, nullptr, DD, DFF);
}

// round 10
// speedup vs baseline: 1.1266x; 1.0288x over previous
#include <cuda_runtime.h>
#include <cuda_bf16.h>
#include <cstdint>

// Problem constants
#define BB    4
#define SS    2048
#define DD    256
#define HH    8
#define DHH   32
#define DFF   512
#define NTOK  (BB*SS)          // 8192
#define EPS   1e-5f
// ATT_SCALE * log2(e) : softmax via ex2
#define ATT_SC2 0.25503540f
#define KSPLIT 2
#define KSEG   (SS/KSPLIT)     // 1024

// smem row pitch in halves (80B): conflict-free + 16B-aligned rows for ldmatrix
#define PITCH 40

// ---------------------------------------------------------------------------
// Scratch (device globals; no allocations allowed)
// ---------------------------------------------------------------------------
__device__ __nv_bfloat16 g_yb [NTOK * DD];        // LN output (bf16)
__device__ __nv_bfloat16 g_ctxb[NTOK * DD];       // attention ctx (bf16)
__device__ float         g_x1 [NTOK * DD];        // residual after attention
__device__ __nv_bfloat16 g_hb [NTOK * DFF];       // FFN hidden (bf16)
__device__ __nv_bfloat16 g_qb[BB*HH * SS * DHH];  // Q bf16 [bh][s][32]
__device__ __nv_bfloat16 g_kb[BB*HH * SS * DHH];
__device__ __nv_bfloat16 g_vb[BB*HH * SS * DHH];
__device__ __nv_bfloat16 g_wqkvb[3*DD * DD];      // bf16 weights
__device__ __nv_bfloat16 g_wprojb[DD * DD];
__device__ __nv_bfloat16 g_w1b[DFF * DD];
__device__ __nv_bfloat16 g_w2b[DD * DFF];
__device__ float g_po[KSPLIT * NTOK * DD];        // split-K partial O (fp32)
__device__ float g_pl[KSPLIT * NTOK * HH];        // split-K partial l

__device__ __forceinline__ uint32_t packbf(float lo, float hi) {
    __nv_bfloat162 t = __floats2bfloat162_rn(lo, hi);
    return *reinterpret_cast<uint32_t*>(&t);
}
__device__ __forceinline__ float ex2(float x) {
    float y;
    asm("ex2.approx.f32 %0, %1;" : "=f"(y) : "f"(x));
    return y;
}
__device__ __forceinline__ void cpa16(uint32_t dst, const void* src) {
    asm volatile("cp.async.cg.shared.global [%0], [%1], 16;" :: "r"(dst), "l"(src));
}

// ---------------------------------------------------------------------------
// One-shot fp32 -> bf16 conversion of ALL weight matrices (single launch)
// ---------------------------------------------------------------------------
__global__ void f2bf_all(const float* __restrict__ s0, const float* __restrict__ s1,
                         const float* __restrict__ s2, const float* __restrict__ s3,
                         __nv_bfloat16* __restrict__ d0, __nv_bfloat16* __restrict__ d1,
                         __nv_bfloat16* __restrict__ d2, __nv_bfloat16* __restrict__ d3) {
    int i = blockIdx.x * 256 + threadIdx.x;     // 0..131071
    int idx = i * 4;
    const float* src; __nv_bfloat16* dst; int off;
    if (idx < 196608)      { src = s0; dst = d0; off = idx; }
    else if (idx < 262144) { src = s1; dst = d1; off = idx - 196608; }
    else if (idx < 393216) { src = s2; dst = d2; off = idx - 262144; }
    else                   { src = s3; dst = d3; off = idx - 393216; }
    float4 v = *(const float4*)(src + off);
    uint2 o;
    o.x = packbf(v.x, v.y);
    o.y = packbf(v.z, v.w);
    *(uint2*)(dst + off) = o;
}

// ---------------------------------------------------------------------------
// LayerNorm -> bf16: one WARP per row (8 rows per 256-thread block)
// ---------------------------------------------------------------------------
__device__ __forceinline__ float warp_sum(float v) {
    #pragma unroll
    for (int o = 16; o > 0; o >>= 1) v += __shfl_xor_sync(0xffffffffu, v, o);
    return v;
}

__global__ __launch_bounds__(256) void ln_kernel(const float* __restrict__ x,
                                                 const float* __restrict__ g,
                                                 const float* __restrict__ b,
                                                 __nv_bfloat16* __restrict__ y) {
    int row  = blockIdx.x * 8 + (threadIdx.x >> 5);
    int lane = threadIdx.x & 31;
    const float* xr = x + (size_t)row * DD + lane * 8;

    float4 v0 = *(const float4*)(xr);
    float4 v1 = *(const float4*)(xr + 4);
    float d[8] = {v0.x, v0.y, v0.z, v0.w, v1.x, v1.y, v1.z, v1.w};

    float s = d[0]+d[1]+d[2]+d[3]+d[4]+d[5]+d[6]+d[7];
    float mean = warp_sum(s) * (1.0f / DD);

    float ss = 0.f;
    #pragma unroll
    for (int j = 0; j < 8; j++) { d[j] -= mean; ss += d[j] * d[j]; }
    float var = warp_sum(ss) * (1.0f / DD);
    float r = rsqrtf(var + EPS);

    float4 g0 = *(const float4*)(g + lane * 8);
    float4 g1 = *(const float4*)(g + lane * 8 + 4);
    float4 b0 = *(const float4*)(b + lane * 8);
    float4 b1 = *(const float4*)(b + lane * 8 + 4);
    float gg[8] = {g0.x, g0.y, g0.z, g0.w, g1.x, g1.y, g1.z, g1.w};
    float bb2[8] = {b0.x, b0.y, b0.z, b0.w, b1.x, b1.y, b1.z, b1.w};

    float o[8];
    #pragma unroll
    for (int j = 0; j < 8; j++) o[j] = d[j] * r * gg[j] + bb2[j];

    uint4 pk;
    pk.x = packbf(o[0], o[1]);
    pk.y = packbf(o[2], o[3]);
    pk.z = packbf(o[4], o[5]);
    pk.w = packbf(o[6], o[7]);
    *(uint4*)&y[(size_t)row * DD + lane * 8] = pk;
}

// ---------------------------------------------------------------------------
// mma helpers
// ---------------------------------------------------------------------------
__device__ __forceinline__ void ldmx4(uint32_t& r0, uint32_t& r1,
                                      uint32_t& r2, uint32_t& r3, uint32_t a) {
    asm volatile("ldmatrix.sync.aligned.m8n8.x4.shared.b16 {%0,%1,%2,%3}, [%4];\n"
                 : "=r"(r0), "=r"(r1), "=r"(r2), "=r"(r3) : "r"(a));
}
__device__ __forceinline__ void ldmx4t(uint32_t& r0, uint32_t& r1,
                                       uint32_t& r2, uint32_t& r3, uint32_t a) {
    asm volatile("ldmatrix.sync.aligned.m8n8.x4.trans.shared.b16 {%0,%1,%2,%3}, [%4];\n"
                 : "=r"(r0), "=r"(r1), "=r"(r2), "=r"(r3) : "r"(a));
}
__device__ __forceinline__ void mma16816(float* c, const uint32_t* a, const uint32_t* b) {
    asm volatile("mma.sync.aligned.m16n8k16.row.col.f32.bf16.bf16.f32 "
                 "{%0,%1,%2,%3}, {%4,%5,%6,%7}, {%8,%9}, {%0,%1,%2,%3};\n"
                 : "+f"(c[0]), "+f"(c[1]), "+f"(c[2]), "+f"(c[3])
                 : "r"(a[0]), "r"(a[1]), "r"(a[2]), "r"(a[3]),
                   "r"(b[0]), "r"(b[1]));
}

// ---------------------------------------------------------------------------
// bf16 tensor-core NT GEMM (R6 version, no prefetch):
// C[n,m] = sum_k A[n,k]*W[m,k] + bias[m] (+ extras)
// Tile: 128 tokens x 64 features, BK=32. 256 threads = 8 warps (4 x 2).
// MODE: 1 = fp32 out + residual, 2 = silu -> bf16 out, 3 = bf16 qkv scatter
// ---------------------------------------------------------------------------
template<int MODE>
__global__ __launch_bounds__(256) void gemm_bf(
        const __nv_bfloat16* __restrict__ A,
        const __nv_bfloat16* __restrict__ W,
        const float* __restrict__ bias,
        const float* __restrict__ res,
        float* __restrict__ C,
        __nv_bfloat16* __restrict__ Ob,
        __nv_bfloat16* __restrict__ Kb,
        __nv_bfloat16* __restrict__ Vb,
        int M, int K) {
    __shared__ __nv_bfloat16 As[128 * PITCH];
    __shared__ __nv_bfloat16 Bs[64 * PITCH];

    int t = threadIdx.x, w = t >> 5, lane = t & 31;
    int wm = w >> 1;
    int wn = w & 1;
    int row0 = blockIdx.y * 128;
    int col0 = blockIdx.x * 64;

    uint32_t abase = (uint32_t)__cvta_generic_to_shared(As);
    uint32_t bbase = (uint32_t)__cvta_generic_to_shared(Bs);

    float c[2][4][4];
    #pragma unroll
    for (int i = 0; i < 2; i++)
        #pragma unroll
        for (int j = 0; j < 4; j++)
            #pragma unroll
            for (int k = 0; k < 4; k++) c[i][j][k] = 0.f;

    for (int k0 = 0; k0 < K; k0 += 32) {
        #pragma unroll
        for (int i = t; i < 512; i += 256) {
            int r = i >> 2, cc = i & 3;
            *(uint4*)&As[r * PITCH + cc * 8] =
                *(const uint4*)&A[(size_t)(row0 + r) * K + k0 + cc * 8];
        }
        {
            int r = t >> 2, cc = t & 3;
            *(uint4*)&Bs[r * PITCH + cc * 8] =
                *(const uint4*)&W[(size_t)(col0 + r) * K + k0 + cc * 8];
        }
        __syncthreads();

        uint32_t bf[2][2][4];
        #pragma unroll
        for (int nt = 0; nt < 2; nt++) {
            int nrow = wn * 32 + nt * 16 + (lane & 7) + ((lane >> 4) << 3);
            #pragma unroll
            for (int ks = 0; ks < 2; ks++) {
                uint32_t ad = bbase + (uint32_t)(nrow * PITCH + ks * 16 + (lane & 8)) * 2;
                ldmx4(bf[nt][ks][0], bf[nt][ks][1], bf[nt][ks][2], bf[nt][ks][3], ad);
            }
        }
        #pragma unroll
        for (int mt = 0; mt < 2; mt++) {
            int arow = wm * 32 + mt * 16 + (lane & 15);
            #pragma unroll
            for (int ks = 0; ks < 2; ks++) {
                uint32_t af[4];
                uint32_t ad = abase + (uint32_t)(arow * PITCH + ks * 16 + ((lane >> 4) << 3)) * 2;
                ldmx4(af[0], af[1], af[2], af[3], ad);
                #pragma unroll
                for (int nt = 0; nt < 2; nt++) {
                    mma16816(c[mt][2 * nt],     af, &bf[nt][ks][0]);
                    mma16816(c[mt][2 * nt + 1], af, &bf[nt][ks][2]);
                }
            }
        }
        __syncthreads();
    }

    #pragma unroll
    for (int mt = 0; mt < 2; mt++) {
        #pragma unroll
        for (int half = 0; half < 2; half++) {
            int row = row0 + wm * 32 + mt * 16 + (lane >> 2) + half * 8;
            #pragma unroll
            for (int n8 = 0; n8 < 4; n8++) {
                int col = col0 + wn * 32 + n8 * 8 + 2 * (lane & 3);
                float v0 = c[mt][n8][2 * half]     + bias[col];
                float v1 = c[mt][n8][2 * half + 1] + bias[col + 1];
                if (MODE == 1) {
                    const float2 r2 = *(const float2*)&res[(size_t)row * M + col];
                    float2 o; o.x = v0 + r2.x; o.y = v1 + r2.y;
                    *(float2*)&C[(size_t)row * M + col] = o;
                } else if (MODE == 2) {
                    v0 = v0 * (1.0f / (1.0f + __expf(-v0)));
                    v1 = v1 * (1.0f / (1.0f + __expf(-v1)));
                    *(__nv_bfloat162*)&Ob[(size_t)row * M + col] =
                        __floats2bfloat162_rn(v0, v1);
                } else {
                    int seg = col >> 8, rem = col & 255;
                    int h = rem >> 5, d = rem & 31;
                    int b = row >> 11, s = row & 2047;
                    __nv_bfloat16* dst = (seg == 0) ? Ob : (seg == 1) ? Kb : Vb;
                    *(__nv_bfloat162*)&dst[((size_t)(b * HH + h) * SS + s) * DHH + d] =
                        __floats2bfloat162_rn(v0, v1);
                }
            }
        }
    }
}

// ---------------------------------------------------------------------------
// Split-K tensor-core flash attention (bf16 mma, fp32 accum, no-max softmax).
// grid (BH=32, S/128=16, KSPLIT=2), block 128 (4 warps; warp owns 32 q rows).
// Each block handles KSEG=1024 keys; writes UNNORMALIZED partial O (fp32)
// and partial l. Linear combination is exact because softmax has no max-shift.
// ---------------------------------------------------------------------------
__global__ __launch_bounds__(128) void attn_mma(const __nv_bfloat16* __restrict__ Qb,
                                                const __nv_bfloat16* __restrict__ Kb,
                                                const __nv_bfloat16* __restrict__ Vb,
                                                float* __restrict__ po,
                                                float* __restrict__ pl) {
    __shared__ __nv_bfloat16 Qs[128 * PITCH];
    __shared__ __nv_bfloat16 Ks[2][64 * PITCH];
    __shared__ __nv_bfloat16 Vs[2][64 * PITCH];

    int bh = blockIdx.x;
    int qt = blockIdx.y;
    int z  = blockIdx.z;
    int t = threadIdx.x, w = t >> 5, lane = t & 31;

    const __nv_bfloat16* qsrc = Qb + ((size_t)bh * SS + qt * 128) * DHH;
    const __nv_bfloat16* ksrc = Kb + ((size_t)bh * SS + z * KSEG) * DHH;
    const __nv_bfloat16* vsrc = Vb + ((size_t)bh * SS + z * KSEG) * DHH;

    uint32_t qbase = (uint32_t)__cvta_generic_to_shared(Qs);
    uint32_t kb_[2] = { (uint32_t)__cvta_generic_to_shared(Ks[0]),
                        (uint32_t)__cvta_generic_to_shared(Ks[1]) };
    uint32_t vb_[2] = { (uint32_t)__cvta_generic_to_shared(Vs[0]),
                        (uint32_t)__cvta_generic_to_shared(Vs[1]) };

    // Q tile: 128 rows x 32 halves = 512 uint4, 4 per thread
    #pragma unroll
    for (int i = t; i < 512; i += 128) {
        int r = i >> 2, s = i & 3;
        *(uint4*)&Qs[r * PITCH + s * 8] = *(const uint4*)&qsrc[r * 32 + s * 8];
    }

    // cp.async per thread per tile: rows (t>>2) and (t>>2)+32, col group t&3
    int lr = t >> 2, ls = t & 3;
    uint32_t so0 = (uint32_t)(lr * PITCH + ls * 8) * 2;
    uint32_t so1 = (uint32_t)((lr + 32) * PITCH + ls * 8) * 2;

    // prologue: tile 0 into buffer 0
    cpa16(kb_[0] + so0, &ksrc[lr * 32 + ls * 8]);
    cpa16(kb_[0] + so1, &ksrc[(lr + 32) * 32 + ls * 8]);
    cpa16(vb_[0] + so0, &vsrc[lr * 32 + ls * 8]);
    cpa16(vb_[0] + so1, &vsrc[(lr + 32) * 32 + ls * 8]);
    asm volatile("cp.async.commit_group;");

    __syncthreads();   // Q ready

    // Q A-fragments: 2 m-tiles x 2 k-steps
    uint32_t qa[2][2][4];
    #pragma unroll
    for (int mt = 0; mt < 2; mt++) {
        int row = w * 32 + mt * 16 + (lane & 15);
        #pragma unroll
        for (int ks = 0; ks < 2; ks++) {
            uint32_t a = qbase + (uint32_t)(row * PITCH + ks * 16 + ((lane >> 4) << 3)) * 2;
            ldmx4(qa[mt][ks][0], qa[mt][ks][1], qa[mt][ks][2], qa[mt][ks][3], a);
        }
    }

    float O[2][4][4];
    #pragma unroll
    for (int mt = 0; mt < 2; mt++)
        #pragma unroll
        for (int i = 0; i < 4; i++)
            #pragma unroll
            for (int j = 0; j < 4; j++) O[mt][i][j] = 0.f;
    float Oext[2][4] = {{0.f,0.f,0.f,0.f},{0.f,0.f,0.f,0.f}};
    const uint32_t onesb[2] = {0x3F803F80u, 0x3F803F80u};

    const int NIT = KSEG / 64;   // 16
    for (int it = 0; it < NIT; it++) {
        int cur = it & 1;
        if (it + 1 < NIT) {
            int koff = (it + 1) * 64;
            int nb = cur ^ 1;
            cpa16(kb_[nb] + so0, &ksrc[(koff + lr) * 32 + ls * 8]);
            cpa16(kb_[nb] + so1, &ksrc[(koff + lr + 32) * 32 + ls * 8]);
            cpa16(vb_[nb] + so0, &vsrc[(koff + lr) * 32 + ls * 8]);
            cpa16(vb_[nb] + so1, &vsrc[(koff + lr + 32) * 32 + ls * 8]);
            asm volatile("cp.async.commit_group;");
            asm volatile("cp.async.wait_group 1;");
        } else {
            asm volatile("cp.async.wait_group 0;");
        }
        __syncthreads();

        uint32_t kba = kb_[cur], vba = vb_[cur];
        #pragma unroll
        for (int j = 0; j < 4; j++) {            // 16-key slabs
            // K fragments (shared across both m-tiles)
            uint32_t b0[4], b1[4];
            int nrow = j * 16 + (lane & 7) + ((lane >> 4) << 3);
            ldmx4(b0[0], b0[1], b0[2], b0[3],
                  kba + (uint32_t)(nrow * PITCH + (lane & 8)) * 2);
            ldmx4(b1[0], b1[1], b1[2], b1[3],
                  kba + (uint32_t)(nrow * PITCH + 16 + (lane & 8)) * 2);

            // S = Q K^T for both m-tiles
            float c[2][2][4];
            #pragma unroll
            for (int mt = 0; mt < 2; mt++) {
                #pragma unroll
                for (int i = 0; i < 4; i++) { c[mt][0][i] = 0.f; c[mt][1][i] = 0.f; }
                mma16816(c[mt][0], qa[mt][0], &b0[0]);
                mma16816(c[mt][0], qa[mt][1], &b1[0]);
                mma16816(c[mt][1], qa[mt][0], &b0[2]);
                mma16816(c[mt][1], qa[mt][1], &b1[2]);
            }

            // softmax + pack P + l via ones-mma
            uint32_t pa[2][4];
            #pragma unroll
            for (int mt = 0; mt < 2; mt++) {
                float p00 = ex2(c[mt][0][0] * ATT_SC2);
                float p01 = ex2(c[mt][0][1] * ATT_SC2);
                float p02 = ex2(c[mt][0][2] * ATT_SC2);
                float p03 = ex2(c[mt][0][3] * ATT_SC2);
                float p10 = ex2(c[mt][1][0] * ATT_SC2);
                float p11 = ex2(c[mt][1][1] * ATT_SC2);
                float p12 = ex2(c[mt][1][2] * ATT_SC2);
                float p13 = ex2(c[mt][1][3] * ATT_SC2);
                pa[mt][0] = packbf(p00, p01);
                pa[mt][1] = packbf(p02, p03);
                pa[mt][2] = packbf(p10, p11);
                pa[mt][3] = packbf(p12, p13);
                mma16816(Oext[mt], pa[mt], onesb);
            }

            // V fragments (shared across both m-tiles)
            int vrow = j * 16 + (lane & 15);
            uint32_t v0[4], v1[4];
            ldmx4t(v0[0], v0[1], v0[2], v0[3],
                   vba + (uint32_t)(vrow * PITCH + ((lane >> 4) << 3)) * 2);
            ldmx4t(v1[0], v1[1], v1[2], v1[3],
                   vba + (uint32_t)(vrow * PITCH + 16 + ((lane >> 4) << 3)) * 2);

            #pragma unroll
            for (int mt = 0; mt < 2; mt++) {
                mma16816(O[mt][0], pa[mt], &v0[0]);
                mma16816(O[mt][1], pa[mt], &v0[2]);
                mma16816(O[mt][2], pa[mt], &v1[0]);
                mma16816(O[mt][3], pa[mt], &v1[2]);
            }
        }
        __syncthreads();
    }

    // epilogue: write UNNORMALIZED partial O + partial l for this split
    int b = bh >> 3, h = bh & 7;
    float* poz = po + (size_t)z * NTOK * DD;
    float* plz = pl + (size_t)z * NTOK * HH;
    #pragma unroll
    for (int mt = 0; mt < 2; mt++) {
        int r0 = qt * 128 + w * 32 + mt * 16 + (lane >> 2);
        int n  = b * SS + r0;
        size_t base = (size_t)n * DD + h * DHH;
        if ((lane & 3) == 0) {
            plz[(size_t)n * HH + h]       = Oext[mt][0];
            plz[(size_t)(n + 8) * HH + h] = Oext[mt][2];
        }
        #pragma unroll
        for (int nt = 0; nt < 4; nt++) {
            int colo = nt * 8 + 2 * (lane & 3);
            float2 u0; u0.x = O[mt][nt][0]; u0.y = O[mt][nt][1];
            *(float2*)&poz[base + colo] = u0;
            float2 u1; u1.x = O[mt][nt][2]; u1.y = O[mt][nt][3];
            *(float2*)&poz[base + 8 * DD + colo] = u1;
        }
    }
}

// ---------------------------------------------------------------------------
// Split-K combine: ctx = (O0 + O1) / (l0 + l1), packed bf16.
// One thread handles 8 consecutive elements (all within one head).
// ---------------------------------------------------------------------------
__global__ __launch_bounds__(256) void attn_combine(const float* __restrict__ po,
                                                    const float* __restrict__ pl,
                                                    __nv_bfloat16* __restrict__ ctx) {
    int i = blockIdx.x * 256 + threadIdx.x;    // 0 .. NTOK*DD/8 - 1
    size_t e = (size_t)i * 8;
    int n = (int)(e >> 8);                     // token
    int col = (int)(e & 255);
    int h = col >> 5;

    float l = pl[(size_t)n * HH + h] + pl[(size_t)NTOK * HH + (size_t)n * HH + h];
    float inv = 1.0f / l;

    float4 a0 = *(const float4*)&po[e];
    float4 a1 = *(const float4*)&po[e + 4];
    float4 b0 = *(const float4*)&po[(size_t)NTOK * DD + e];
    float4 b1 = *(const float4*)&po[(size_t)NTOK * DD + e + 4];

    uint4 pk;
    pk.x = packbf((a0.x + b0.x) * inv, (a0.y + b0.y) * inv);
    pk.y = packbf((a0.z + b0.z) * inv, (a0.w + b0.w) * inv);
    pk.z = packbf((a1.x + b1.x) * inv, (a1.y + b1.y) * inv);
    pk.w = packbf((a1.z + b1.z) * inv, (a1.w + b1.w) * inv);
    *(uint4*)&ctx[e] = pk;
}

// ---------------------------------------------------------------------------
// Launch
// ---------------------------------------------------------------------------
extern "C" void kernel_launch(void* const* d_in, const int* in_sizes, int n_in,
                              void* d_out, int out_size) {
    const float* x      = (const float*)d_in[0];
    const float* ln1_g  = (const float*)d_in[1];
    const float* ln1_b  = (const float*)d_in[2];
    const float* w_qkv  = (const float*)d_in[3];
    const float* b_qkv  = (const float*)d_in[4];
    const float* w_proj = (const float*)d_in[5];
    const float* b_proj = (const float*)d_in[6];
    const float* ln2_g  = (const float*)d_in[7];
    const float* ln2_b  = (const float*)d_in[8];
    const float* w1     = (const float*)d_in[9];
    const float* b1     = (const float*)d_in[10];
    const float* w2     = (const float*)d_in[11];
    const float* b2     = (const float*)d_in[12];
    float* out = (float*)d_out;

    __nv_bfloat16 *yb, *ctxb, *hb, *qb, *kb, *vb, *wqkvb, *wprojb, *w1b, *w2b;
    float *x1, *po, *pl;
    cudaGetSymbolAddress((void**)&yb,     g_yb);
    cudaGetSymbolAddress((void**)&ctxb,   g_ctxb);
    cudaGetSymbolAddress((void**)&x1,     g_x1);
    cudaGetSymbolAddress((void**)&hb,     g_hb);
    cudaGetSymbolAddress((void**)&qb,     g_qb);
    cudaGetSymbolAddress((void**)&kb,     g_kb);
    cudaGetSymbolAddress((void**)&vb,     g_vb);
    cudaGetSymbolAddress((void**)&wqkvb,  g_wqkvb);
    cudaGetSymbolAddress((void**)&wprojb, g_wprojb);
    cudaGetSymbolAddress((void**)&w1b,    g_w1b);
    cudaGetSymbolAddress((void**)&w2b,    g_w2b);
    cudaGetSymbolAddress((void**)&po,     g_po);
    cudaGetSymbolAddress((void**)&pl,     g_pl);

    // 0. all weights fp32 -> bf16, one launch
    f2bf_all<<<512, 256>>>(w_qkv, w_proj, w1, w2, wqkvb, wprojb, w1b, w2b);

    // 1. LN1 -> bf16
    ln_kernel<<<NTOK/8, 256>>>(x, ln1_g, ln1_b, yb);
    // 2. QKV GEMM -> bf16 Q/K/V [bh][s][32]
    gemm_bf<3><<<dim3(768/64, NTOK/128), 256>>>(yb, wqkvb, b_qkv, nullptr, nullptr,
                                                qb, kb, vb, 3*DD, DD);
    // 3. split-K attention -> partial O/l, then combine -> ctx bf16
    attn_mma<<<dim3(BB*HH, SS/128, KSPLIT), 128>>>(qb, kb, vb, po, pl);
    attn_combine<<<NTOK*DD/8/256, 256>>>(po, pl, ctxb);
    // 4. proj + residual -> x1 fp32
    gemm_bf<1><<<dim3(DD/64, NTOK/128), 256>>>(ctxb, wprojb, b_proj, x, x1,
                                               nullptr, nullptr, nullptr, DD, DD);
    // 5. LN2 -> bf16
    ln_kernel<<<NTOK/8, 256>>>(x1, ln2_g, ln2_b, yb);
    // 6. FFN1 + silu -> bf16 h
    gemm_bf<2><<<dim3(DFF/64, NTOK/128), 256>>>(yb, w1b, b1, nullptr, nullptr,
                                                hb, nullptr, nullptr, DFF, DD);
    // 7. FFN2 + residual -> out fp32
    gemm_bf<1><<<dim3(DD/64, NTOK/128), 256>>>(hb, w2b, b2, x1, out,
                                               nullptr, nullptr, nullptr, DD, DFF);
}

// round 11
// speedup vs baseline: 1.1622x; 1.0316x over previous
#include <cuda_runtime.h>
#include <cuda_bf16.h>
#include <cstdint>

// Problem constants
#define BB    4
#define SS    2048
#define DD    256
#define HH    8
#define DHH   32
#define DFF   512
#define NTOK  (BB*SS)          // 8192
#define EPS   1e-5f
// ATT_SCALE * log2(e) : softmax via ex2
#define ATT_SC2 0.25503540f
#define KSPLIT 2
#define KSEG   (SS/KSPLIT)     // 1024

// smem row pitch in halves (80B): conflict-free + 16B-aligned rows for ldmatrix
#define PITCH 40

// ---------------------------------------------------------------------------
// Scratch (device globals; no allocations allowed)
// ---------------------------------------------------------------------------
__device__ __nv_bfloat16 g_yb [NTOK * DD];        // LN output (bf16)
__device__ __nv_bfloat16 g_ctxb[NTOK * DD];       // attention ctx (bf16)
__device__ float         g_x1 [NTOK * DD];        // residual after attention
__device__ __nv_bfloat16 g_hb [NTOK * DFF];       // FFN hidden (bf16)
__device__ __nv_bfloat16 g_qb[BB*HH * SS * DHH];  // Q bf16 [bh][s][32]
__device__ __nv_bfloat16 g_kb[BB*HH * SS * DHH];
__device__ __nv_bfloat16 g_vb[BB*HH * SS * DHH];
__device__ __nv_bfloat16 g_wqkvb[3*DD * DD];      // bf16 weights
__device__ __nv_bfloat16 g_wprojb[DD * DD];
__device__ __nv_bfloat16 g_w1b[DFF * DD];
__device__ __nv_bfloat16 g_w2b[DD * DFF];
__device__ float g_po[KSPLIT * NTOK * DD];        // split-K partial O (fp32)
__device__ float g_pl[KSPLIT * NTOK * HH];        // split-K partial l

__device__ __forceinline__ uint32_t packbf(float lo, float hi) {
    __nv_bfloat162 t = __floats2bfloat162_rn(lo, hi);
    return *reinterpret_cast<uint32_t*>(&t);
}
__device__ __forceinline__ float ex2(float x) {
    float y;
    asm("ex2.approx.f32 %0, %1;" : "=f"(y) : "f"(x));
    return y;
}
__device__ __forceinline__ void cpa16(uint32_t dst, const void* src) {
    asm volatile("cp.async.cg.shared.global [%0], [%1], 16;" :: "r"(dst), "l"(src));
}

// ---------------------------------------------------------------------------
// One-shot fp32 -> bf16 conversion of ALL weight matrices.
// 16 elems/thread (4 independent float4 loads -> MLP=4). 128 blocks.
// Segment boundaries (196608/262144/393216) are multiples of 16.
// ---------------------------------------------------------------------------
__global__ void f2bf_all(const float* __restrict__ s0, const float* __restrict__ s1,
                         const float* __restrict__ s2, const float* __restrict__ s3,
                         __nv_bfloat16* __restrict__ d0, __nv_bfloat16* __restrict__ d1,
                         __nv_bfloat16* __restrict__ d2, __nv_bfloat16* __restrict__ d3) {
    int i = blockIdx.x * 256 + threadIdx.x;     // 0..32767
    int idx = i * 16;
    const float* src; __nv_bfloat16* dst; int off;
    if (idx < 196608)      { src = s0; dst = d0; off = idx; }
    else if (idx < 262144) { src = s1; dst = d1; off = idx - 196608; }
    else if (idx < 393216) { src = s2; dst = d2; off = idx - 262144; }
    else                   { src = s3; dst = d3; off = idx - 393216; }
    float4 v0 = *(const float4*)(src + off);
    float4 v1 = *(const float4*)(src + off + 4);
    float4 v2 = *(const float4*)(src + off + 8);
    float4 v3 = *(const float4*)(src + off + 12);
    uint4 o0, o1;
    o0.x = packbf(v0.x, v0.y); o0.y = packbf(v0.z, v0.w);
    o0.z = packbf(v1.x, v1.y); o0.w = packbf(v1.z, v1.w);
    o1.x = packbf(v2.x, v2.y); o1.y = packbf(v2.z, v2.w);
    o1.z = packbf(v3.x, v3.y); o1.w = packbf(v3.z, v3.w);
    *(uint4*)(dst + off)     = o0;
    *(uint4*)(dst + off + 8) = o1;
}

// ---------------------------------------------------------------------------
// LayerNorm -> bf16: one WARP per row (8 rows per 256-thread block)
// ---------------------------------------------------------------------------
__device__ __forceinline__ float warp_sum(float v) {
    #pragma unroll
    for (int o = 16; o > 0; o >>= 1) v += __shfl_xor_sync(0xffffffffu, v, o);
    return v;
}

__global__ __launch_bounds__(256) void ln_kernel(const float* __restrict__ x,
                                                 const float* __restrict__ g,
                                                 const float* __restrict__ b,
                                                 __nv_bfloat16* __restrict__ y) {
    int row  = blockIdx.x * 8 + (threadIdx.x >> 5);
    int lane = threadIdx.x & 31;
    const float* xr = x + (size_t)row * DD + lane * 8;

    float4 v0 = *(const float4*)(xr);
    float4 v1 = *(const float4*)(xr + 4);
    float d[8] = {v0.x, v0.y, v0.z, v0.w, v1.x, v1.y, v1.z, v1.w};

    float s = d[0]+d[1]+d[2]+d[3]+d[4]+d[5]+d[6]+d[7];
    float mean = warp_sum(s) * (1.0f / DD);

    float ss = 0.f;
    #pragma unroll
    for (int j = 0; j < 8; j++) { d[j] -= mean; ss += d[j] * d[j]; }
    float var = warp_sum(ss) * (1.0f / DD);
    float r = rsqrtf(var + EPS);

    float4 g0 = *(const float4*)(g + lane * 8);
    float4 g1 = *(const float4*)(g + lane * 8 + 4);
    float4 b0 = *(const float4*)(b + lane * 8);
    float4 b1 = *(const float4*)(b + lane * 8 + 4);
    float gg[8] = {g0.x, g0.y, g0.z, g0.w, g1.x, g1.y, g1.z, g1.w};
    float bb2[8] = {b0.x, b0.y, b0.z, b0.w, b1.x, b1.y, b1.z, b1.w};

    float o[8];
    #pragma unroll
    for (int j = 0; j < 8; j++) o[j] = d[j] * r * gg[j] + bb2[j];

    uint4 pk;
    pk.x = packbf(o[0], o[1]);
    pk.y = packbf(o[2], o[3]);
    pk.z = packbf(o[4], o[5]);
    pk.w = packbf(o[6], o[7]);
    *(uint4*)&y[(size_t)row * DD + lane * 8] = pk;
}

// ---------------------------------------------------------------------------
// mma helpers
// ---------------------------------------------------------------------------
__device__ __forceinline__ void ldmx4(uint32_t& r0, uint32_t& r1,
                                      uint32_t& r2, uint32_t& r3, uint32_t a) {
    asm volatile("ldmatrix.sync.aligned.m8n8.x4.shared.b16 {%0,%1,%2,%3}, [%4];\n"
                 : "=r"(r0), "=r"(r1), "=r"(r2), "=r"(r3) : "r"(a));
}
__device__ __forceinline__ void ldmx4t(uint32_t& r0, uint32_t& r1,
                                       uint32_t& r2, uint32_t& r3, uint32_t a) {
    asm volatile("ldmatrix.sync.aligned.m8n8.x4.trans.shared.b16 {%0,%1,%2,%3}, [%4];\n"
                 : "=r"(r0), "=r"(r1), "=r"(r2), "=r"(r3) : "r"(a));
}
__device__ __forceinline__ void mma16816(float* c, const uint32_t* a, const uint32_t* b) {
    asm volatile("mma.sync.aligned.m16n8k16.row.col.f32.bf16.bf16.f32 "
                 "{%0,%1,%2,%3}, {%4,%5,%6,%7}, {%8,%9}, {%0,%1,%2,%3};\n"
                 : "+f"(c[0]), "+f"(c[1]), "+f"(c[2]), "+f"(c[3])
                 : "r"(a[0]), "r"(a[1]), "r"(a[2]), "r"(a[3]),
                   "r"(b[0]), "r"(b[1]));
}

// ---------------------------------------------------------------------------
// bf16 tensor-core NT GEMM with cp.async double-buffered tiles:
// C[n,m] = sum_k A[n,k]*W[m,k] + bias[m] (+ extras)
// Tile: 128 tokens x 64 features, BK=32. 256 threads = 8 warps (4 x 2).
// MODE: 1 = fp32 out + residual, 2 = silu -> bf16 out, 3 = bf16 qkv scatter
// ---------------------------------------------------------------------------
template<int MODE>
__global__ __launch_bounds__(256) void gemm_bf(
        const __nv_bfloat16* __restrict__ A,
        const __nv_bfloat16* __restrict__ W,
        const float* __restrict__ bias,
        const float* __restrict__ res,
        float* __restrict__ C,
        __nv_bfloat16* __restrict__ Ob,
        __nv_bfloat16* __restrict__ Kb,
        __nv_bfloat16* __restrict__ Vb,
        int M, int K) {
    __shared__ __nv_bfloat16 As[2][128 * PITCH];
    __shared__ __nv_bfloat16 Bs[2][64 * PITCH];

    int t = threadIdx.x, w = t >> 5, lane = t & 31;
    int wm = w >> 1;
    int wn = w & 1;
    int row0 = blockIdx.y * 128;
    int col0 = blockIdx.x * 64;

    uint32_t ab_[2] = { (uint32_t)__cvta_generic_to_shared(As[0]),
                        (uint32_t)__cvta_generic_to_shared(As[1]) };
    uint32_t bb_[2] = { (uint32_t)__cvta_generic_to_shared(Bs[0]),
                        (uint32_t)__cvta_generic_to_shared(Bs[1]) };

    // cp.async indices: A 2 per thread, B 1 per thread
    int ar = t >> 1, ac = (t & 1) * 2;
    int br = t >> 2, bc = t & 3;
    uint32_t soA0 = (uint32_t)(ar * PITCH + ac * 8) * 2;
    uint32_t soA1 = (uint32_t)(ar * PITCH + (ac + 1) * 8) * 2;
    uint32_t soB  = (uint32_t)(br * PITCH + bc * 8) * 2;
    const __nv_bfloat16* asrc = A + (size_t)(row0 + ar) * K;
    const __nv_bfloat16* bsrc = W + (size_t)(col0 + br) * K;

    float c[2][4][4];
    #pragma unroll
    for (int i = 0; i < 2; i++)
        #pragma unroll
        for (int j = 0; j < 4; j++)
            #pragma unroll
            for (int k = 0; k < 4; k++) c[i][j][k] = 0.f;

    // prologue: stage 0
    cpa16(ab_[0] + soA0, asrc + ac * 8);
    cpa16(ab_[0] + soA1, asrc + (ac + 1) * 8);
    cpa16(bb_[0] + soB,  bsrc + bc * 8);
    asm volatile("cp.async.commit_group;");

    int NK = K >> 5;
    for (int it = 0; it < NK; it++) {
        int cur = it & 1;
        if (it + 1 < NK) {
            int nb = cur ^ 1;
            int k0 = (it + 1) * 32;
            cpa16(ab_[nb] + soA0, asrc + k0 + ac * 8);
            cpa16(ab_[nb] + soA1, asrc + k0 + (ac + 1) * 8);
            cpa16(bb_[nb] + soB,  bsrc + k0 + bc * 8);
            asm volatile("cp.async.commit_group;");
            asm volatile("cp.async.wait_group 1;");
        } else {
            asm volatile("cp.async.wait_group 0;");
        }
        __syncthreads();

        uint32_t abase = ab_[cur], bbase = bb_[cur];
        uint32_t bf[2][2][4];
        #pragma unroll
        for (int nt = 0; nt < 2; nt++) {
            int nrow = wn * 32 + nt * 16 + (lane & 7) + ((lane >> 4) << 3);
            #pragma unroll
            for (int ks = 0; ks < 2; ks++) {
                uint32_t ad = bbase + (uint32_t)(nrow * PITCH + ks * 16 + (lane & 8)) * 2;
                ldmx4(bf[nt][ks][0], bf[nt][ks][1], bf[nt][ks][2], bf[nt][ks][3], ad);
            }
        }
        #pragma unroll
        for (int mt = 0; mt < 2; mt++) {
            int arow = wm * 32 + mt * 16 + (lane & 15);
            #pragma unroll
            for (int ks = 0; ks < 2; ks++) {
                uint32_t af[4];
                uint32_t ad = abase + (uint32_t)(arow * PITCH + ks * 16 + ((lane >> 4) << 3)) * 2;
                ldmx4(af[0], af[1], af[2], af[3], ad);
                #pragma unroll
                for (int nt = 0; nt < 2; nt++) {
                    mma16816(c[mt][2 * nt],     af, &bf[nt][ks][0]);
                    mma16816(c[mt][2 * nt + 1], af, &bf[nt][ks][2]);
                }
            }
        }
        __syncthreads();
    }

    #pragma unroll
    for (int mt = 0; mt < 2; mt++) {
        #pragma unroll
        for (int half = 0; half < 2; half++) {
            int row = row0 + wm * 32 + mt * 16 + (lane >> 2) + half * 8;
            #pragma unroll
            for (int n8 = 0; n8 < 4; n8++) {
                int col = col0 + wn * 32 + n8 * 8 + 2 * (lane & 3);
                float v0 = c[mt][n8][2 * half]     + bias[col];
                float v1 = c[mt][n8][2 * half + 1] + bias[col + 1];
                if (MODE == 1) {
                    const float2 r2 = *(const float2*)&res[(size_t)row * M + col];
                    float2 o; o.x = v0 + r2.x; o.y = v1 + r2.y;
                    *(float2*)&C[(size_t)row * M + col] = o;
                } else if (MODE == 2) {
                    v0 = v0 * (1.0f / (1.0f + __expf(-v0)));
                    v1 = v1 * (1.0f / (1.0f + __expf(-v1)));
                    *(__nv_bfloat162*)&Ob[(size_t)row * M + col] =
                        __floats2bfloat162_rn(v0, v1);
                } else {
                    int seg = col >> 8, rem = col & 255;
                    int h = rem >> 5, d = rem & 31;
                    int b = row >> 11, s = row & 2047;
                    __nv_bfloat16* dst = (seg == 0) ? Ob : (seg == 1) ? Kb : Vb;
                    *(__nv_bfloat162*)&dst[((size_t)(b * HH + h) * SS + s) * DHH + d] =
                        __floats2bfloat162_rn(v0, v1);
                }
            }
        }
    }
}

// ---------------------------------------------------------------------------
// Split-K tensor-core flash attention (bf16 mma, fp32 accum, no-max softmax).
// grid (BH=32, S/128=16, KSPLIT=2), block 128 (4 warps; warp owns 32 q rows).
// Writes UNNORMALIZED partial O (fp32) and partial l.
// ---------------------------------------------------------------------------
__global__ __launch_bounds__(128) void attn_mma(const __nv_bfloat16* __restrict__ Qb,
                                                const __nv_bfloat16* __restrict__ Kb,
                                                const __nv_bfloat16* __restrict__ Vb,
                                                float* __restrict__ po,
                                                float* __restrict__ pl) {
    __shared__ __nv_bfloat16 Qs[128 * PITCH];
    __shared__ __nv_bfloat16 Ks[2][64 * PITCH];
    __shared__ __nv_bfloat16 Vs[2][64 * PITCH];

    int bh = blockIdx.x;
    int qt = blockIdx.y;
    int z  = blockIdx.z;
    int t = threadIdx.x, w = t >> 5, lane = t & 31;

    const __nv_bfloat16* qsrc = Qb + ((size_t)bh * SS + qt * 128) * DHH;
    const __nv_bfloat16* ksrc = Kb + ((size_t)bh * SS + z * KSEG) * DHH;
    const __nv_bfloat16* vsrc = Vb + ((size_t)bh * SS + z * KSEG) * DHH;

    uint32_t qbase = (uint32_t)__cvta_generic_to_shared(Qs);
    uint32_t kb_[2] = { (uint32_t)__cvta_generic_to_shared(Ks[0]),
                        (uint32_t)__cvta_generic_to_shared(Ks[1]) };
    uint32_t vb_[2] = { (uint32_t)__cvta_generic_to_shared(Vs[0]),
                        (uint32_t)__cvta_generic_to_shared(Vs[1]) };

    #pragma unroll
    for (int i = t; i < 512; i += 128) {
        int r = i >> 2, s = i & 3;
        *(uint4*)&Qs[r * PITCH + s * 8] = *(const uint4*)&qsrc[r * 32 + s * 8];
    }

    int lr = t >> 2, ls = t & 3;
    uint32_t so0 = (uint32_t)(lr * PITCH + ls * 8) * 2;
    uint32_t so1 = (uint32_t)((lr + 32) * PITCH + ls * 8) * 2;

    cpa16(kb_[0] + so0, &ksrc[lr * 32 + ls * 8]);
    cpa16(kb_[0] + so1, &ksrc[(lr + 32) * 32 + ls * 8]);
    cpa16(vb_[0] + so0, &vsrc[lr * 32 + ls * 8]);
    cpa16(vb_[0] + so1, &vsrc[(lr + 32) * 32 + ls * 8]);
    asm volatile("cp.async.commit_group;");

    __syncthreads();   // Q ready

    uint32_t qa[2][2][4];
    #pragma unroll
    for (int mt = 0; mt < 2; mt++) {
        int row = w * 32 + mt * 16 + (lane & 15);
        #pragma unroll
        for (int ks = 0; ks < 2; ks++) {
            uint32_t a = qbase + (uint32_t)(row * PITCH + ks * 16 + ((lane >> 4) << 3)) * 2;
            ldmx4(qa[mt][ks][0], qa[mt][ks][1], qa[mt][ks][2], qa[mt][ks][3], a);
        }
    }

    float O[2][4][4];
    #pragma unroll
    for (int mt = 0; mt < 2; mt++)
        #pragma unroll
        for (int i = 0; i < 4; i++)
            #pragma unroll
            for (int j = 0; j < 4; j++) O[mt][i][j] = 0.f;
    float Oext[2][4] = {{0.f,0.f,0.f,0.f},{0.f,0.f,0.f,0.f}};
    const uint32_t onesb[2] = {0x3F803F80u, 0x3F803F80u};

    const int NIT = KSEG / 64;   // 16
    for (int it = 0; it < NIT; it++) {
        int cur = it & 1;
        if (it + 1 < NIT) {
            int koff = (it + 1) * 64;
            int nb = cur ^ 1;
            cpa16(kb_[nb] + so0, &ksrc[(koff + lr) * 32 + ls * 8]);
            cpa16(kb_[nb] + so1, &ksrc[(koff + lr + 32) * 32 + ls * 8]);
            cpa16(vb_[nb] + so0, &vsrc[(koff + lr) * 32 + ls * 8]);
            cpa16(vb_[nb] + so1, &vsrc[(koff + lr + 32) * 32 + ls * 8]);
            asm volatile("cp.async.commit_group;");
            asm volatile("cp.async.wait_group 1;");
        } else {
            asm volatile("cp.async.wait_group 0;");
        }
        __syncthreads();

        uint32_t kba = kb_[cur], vba = vb_[cur];
        #pragma unroll
        for (int j = 0; j < 4; j++) {            // 16-key slabs
            uint32_t b0[4], b1[4];
            int nrow = j * 16 + (lane & 7) + ((lane >> 4) << 3);
            ldmx4(b0[0], b0[1], b0[2], b0[3],
                  kba + (uint32_t)(nrow * PITCH + (lane & 8)) * 2);
            ldmx4(b1[0], b1[1], b1[2], b1[3],
                  kba + (uint32_t)(nrow * PITCH + 16 + (lane & 8)) * 2);

            float c[2][2][4];
            #pragma unroll
            for (int mt = 0; mt < 2; mt++) {
                #pragma unroll
                for (int i = 0; i < 4; i++) { c[mt][0][i] = 0.f; c[mt][1][i] = 0.f; }
                mma16816(c[mt][0], qa[mt][0], &b0[0]);
                mma16816(c[mt][0], qa[mt][1], &b1[0]);
                mma16816(c[mt][1], qa[mt][0], &b0[2]);
                mma16816(c[mt][1], qa[mt][1], &b1[2]);
            }

            uint32_t pa[2][4];
            #pragma unroll
            for (int mt = 0; mt < 2; mt++) {
                float p00 = ex2(c[mt][0][0] * ATT_SC2);
                float p01 = ex2(c[mt][0][1] * ATT_SC2);
                float p02 = ex2(c[mt][0][2] * ATT_SC2);
                float p03 = ex2(c[mt][0][3] * ATT_SC2);
                float p10 = ex2(c[mt][1][0] * ATT_SC2);
                float p11 = ex2(c[mt][1][1] * ATT_SC2);
                float p12 = ex2(c[mt][1][2] * ATT_SC2);
                float p13 = ex2(c[mt][1][3] * ATT_SC2);
                pa[mt][0] = packbf(p00, p01);
                pa[mt][1] = packbf(p02, p03);
                pa[mt][2] = packbf(p10, p11);
                pa[mt][3] = packbf(p12, p13);
                mma16816(Oext[mt], pa[mt], onesb);
            }

            int vrow = j * 16 + (lane & 15);
            uint32_t v0[4], v1[4];
            ldmx4t(v0[0], v0[1], v0[2], v0[3],
                   vba + (uint32_t)(vrow * PITCH + ((lane >> 4) << 3)) * 2);
            ldmx4t(v1[0], v1[1], v1[2], v1[3],
                   vba + (uint32_t)(vrow * PITCH + 16 + ((lane >> 4) << 3)) * 2);

            #pragma unroll
            for (int mt = 0; mt < 2; mt++) {
                mma16816(O[mt][0], pa[mt], &v0[0]);
                mma16816(O[mt][1], pa[mt], &v0[2]);
                mma16816(O[mt][2], pa[mt], &v1[0]);
                mma16816(O[mt][3], pa[mt], &v1[2]);
            }
        }
        __syncthreads();
    }

    int b = bh >> 3, h = bh & 7;
    float* poz = po + (size_t)z * NTOK * DD;
    float* plz = pl + (size_t)z * NTOK * HH;
    #pragma unroll
    for (int mt = 0; mt < 2; mt++) {
        int r0 = qt * 128 + w * 32 + mt * 16 + (lane >> 2);
        int n  = b * SS + r0;
        size_t base = (size_t)n * DD + h * DHH;
        if ((lane & 3) == 0) {
            plz[(size_t)n * HH + h]       = Oext[mt][0];
            plz[(size_t)(n + 8) * HH + h] = Oext[mt][2];
        }
        #pragma unroll
        for (int nt = 0; nt < 4; nt++) {
            int colo = nt * 8 + 2 * (lane & 3);
            float2 u0; u0.x = O[mt][nt][0]; u0.y = O[mt][nt][1];
            *(float2*)&poz[base + colo] = u0;
            float2 u1; u1.x = O[mt][nt][2]; u1.y = O[mt][nt][3];
            *(float2*)&poz[base + 8 * DD + colo] = u1;
        }
    }
}

// ---------------------------------------------------------------------------
// Split-K combine: ctx = (O0 + O1) / (l0 + l1), packed bf16.
// ---------------------------------------------------------------------------
__global__ __launch_bounds__(256) void attn_combine(const float* __restrict__ po,
                                                    const float* __restrict__ pl,
                                                    __nv_bfloat16* __restrict__ ctx) {
    int i = blockIdx.x * 256 + threadIdx.x;    // 0 .. NTOK*DD/8 - 1
    size_t e = (size_t)i * 8;
    int n = (int)(e >> 8);                     // token
    int col = (int)(e & 255);
    int h = col >> 5;

    float l = pl[(size_t)n * HH + h] + pl[(size_t)NTOK * HH + (size_t)n * HH + h];
    float inv = 1.0f / l;

    float4 a0 = *(const float4*)&po[e];
    float4 a1 = *(const float4*)&po[e + 4];
    float4 b0 = *(const float4*)&po[(size_t)NTOK * DD + e];
    float4 b1 = *(const float4*)&po[(size_t)NTOK * DD + e + 4];

    uint4 pk;
    pk.x = packbf((a0.x + b0.x) * inv, (a0.y + b0.y) * inv);
    pk.y = packbf((a0.z + b0.z) * inv, (a0.w + b0.w) * inv);
    pk.z = packbf((a1.x + b1.x) * inv, (a1.y + b1.y) * inv);
    pk.w = packbf((a1.z + b1.z) * inv, (a1.w + b1.w) * inv);
    *(uint4*)&ctx[e] = pk;
}

// ---------------------------------------------------------------------------
// Launch
// ---------------------------------------------------------------------------
extern "C" void kernel_launch(void* const* d_in, const int* in_sizes, int n_in,
                              void* d_out, int out_size) {
    const float* x      = (const float*)d_in[0];
    const float* ln1_g  = (const float*)d_in[1];
    const float* ln1_b  = (const float*)d_in[2];
    const float* w_qkv  = (const float*)d_in[3];
    const float* b_qkv  = (const float*)d_in[4];
    const float* w_proj = (const float*)d_in[5];
    const float* b_proj = (const float*)d_in[6];
    const float* ln2_g  = (const float*)d_in[7];
    const float* ln2_b  = (const float*)d_in[8];
    const float* w1     = (const float*)d_in[9];
    const float* b1     = (const float*)d_in[10];
    const float* w2     = (const float*)d_in[11];
    const float* b2     = (const float*)d_in[12];
    float* out = (float*)d_out;

    __nv_bfloat16 *yb, *ctxb, *hb, *qb, *kb, *vb, *wqkvb, *wprojb, *w1b, *w2b;
    float *x1, *po, *pl;
    cudaGetSymbolAddress((void**)&yb,     g_yb);
    cudaGetSymbolAddress((void**)&ctxb,   g_ctxb);
    cudaGetSymbolAddress((void**)&x1,     g_x1);
    cudaGetSymbolAddress((void**)&hb,     g_hb);
    cudaGetSymbolAddress((void**)&qb,     g_qb);
    cudaGetSymbolAddress((void**)&kb,     g_kb);
    cudaGetSymbolAddress((void**)&vb,     g_vb);
    cudaGetSymbolAddress((void**)&wqkvb,  g_wqkvb);
    cudaGetSymbolAddress((void**)&wprojb, g_wprojb);
    cudaGetSymbolAddress((void**)&w1b,    g_w1b);
    cudaGetSymbolAddress((void**)&w2b,    g_w2b);
    cudaGetSymbolAddress((void**)&po,     g_po);
    cudaGetSymbolAddress((void**)&pl,     g_pl);

    // 0. all weights fp32 -> bf16, one launch (16 elems/thread)
    f2bf_all<<<128, 256>>>(w_qkv, w_proj, w1, w2, wqkvb, wprojb, w1b, w2b);

    // 1. LN1 -> bf16
    ln_kernel<<<NTOK/8, 256>>>(x, ln1_g, ln1_b, yb);
    // 2. QKV GEMM -> bf16 Q/K/V [bh][s][32]
    gemm_bf<3><<<dim3(768/64, NTOK/128), 256>>>(yb, wqkvb, b_qkv, nullptr, nullptr,
                                                qb, kb, vb, 3*DD, DD);
    // 3. split-K attention -> partial O/l, then combine -> ctx bf16
    attn_mma<<<dim3(BB*HH, SS/128, KSPLIT), 128>>>(qb, kb, vb, po, pl);
    attn_combine<<<NTOK*DD/8/256, 256>>>(po, pl, ctxb);
    // 4. proj + residual -> x1 fp32
    gemm_bf<1><<<dim3(DD/64, NTOK/128), 256>>>(ctxb, wprojb, b_proj, x, x1,
                                               nullptr, nullptr, nullptr, DD, DD);
    // 5. LN2 -> bf16
    ln_kernel<<<NTOK/8, 256>>>(x1, ln2_g, ln2_b, yb);
    // 6. FFN1 + silu -> bf16 h
    gemm_bf<2><<<dim3(DFF/64, NTOK/128), 256>>>(yb, w1b, b1, nullptr, nullptr,
                                                hb, nullptr, nullptr, DFF, DD);
    // 7. FFN2 + residual -> out fp32
    gemm_bf<1><<<dim3(DD/64, NTOK/128), 256>>>(hb, w2b, b2, x1, out,
                                               nullptr, nullptr, nullptr, DD, DFF);
}

// round 12
// speedup vs baseline: 1.1795x; 1.0149x over previous
#include <cuda_runtime.h>
#include <cuda_bf16.h>
#include <cuda_fp16.h>
#include <cstdint>

// Problem constants
#define BB    4
#define SS    2048
#define DD    256
#define HH    8
#define DHH   32
#define DFF   512
#define NTOK  (BB*SS)          // 8192
#define EPS   1e-5f
// softmax scale * log2(e), folded into Q at QKV epilogue
#define ATT_SC2 0.25503540f
#define KSPLIT 2
#define KSEG   (SS/KSPLIT)     // 1024

// smem row pitch in halves (80B): conflict-free + 16B-aligned rows for ldmatrix
#define PITCH 40

// ---------------------------------------------------------------------------
// Scratch (device globals; no allocations allowed)
// ---------------------------------------------------------------------------
__device__ __nv_bfloat16 g_yb [NTOK * DD];        // LN output (bf16)
__device__ float         g_x1 [NTOK * DD];        // residual after attention
__device__ __nv_bfloat16 g_hb [NTOK * DFF];       // FFN hidden (bf16)
__device__ __nv_bfloat16 g_qb[BB*HH * SS * DHH];  // Q bf16 (pre-scaled) [bh][s][32]
__device__ __nv_bfloat16 g_kb[BB*HH * SS * DHH];  // K bf16
__device__ __half        g_vh[BB*HH * SS * DHH];  // V fp16
__device__ __nv_bfloat16 g_wqkvb[3*DD * DD];      // bf16 weights
__device__ __nv_bfloat16 g_wprojb[DD * DD];
__device__ __nv_bfloat16 g_w1b[DFF * DD];
__device__ __nv_bfloat16 g_w2b[DD * DFF];
__device__ float g_po[KSPLIT * NTOK * DD];        // split-K partial O (fp32)
__device__ float g_pl[KSPLIT * NTOK * HH];        // split-K partial l

__device__ __forceinline__ uint32_t packbf(float lo, float hi) {
    __nv_bfloat162 t = __floats2bfloat162_rn(lo, hi);
    return *reinterpret_cast<uint32_t*>(&t);
}
// pack 2 fp32 exponent args -> f16x2, then 2^x on both halves (1 MUFU op)
__device__ __forceinline__ uint32_t exp2h2(float lo, float hi) {
    uint32_t d;
    asm("cvt.rn.f16x2.f32 %0, %1, %2;" : "=r"(d) : "f"(hi), "f"(lo));
    asm("ex2.approx.f16x2 %0, %0;" : "+r"(d));
    return d;
}
__device__ __forceinline__ void cpa16(uint32_t dst, const void* src) {
    asm volatile("cp.async.cg.shared.global [%0], [%1], 16;" :: "r"(dst), "l"(src));
}

// ---------------------------------------------------------------------------
// One-shot fp32 -> bf16 conversion of ALL weight matrices.
// ---------------------------------------------------------------------------
__global__ void f2bf_all(const float* __restrict__ s0, const float* __restrict__ s1,
                         const float* __restrict__ s2, const float* __restrict__ s3,
                         __nv_bfloat16* __restrict__ d0, __nv_bfloat16* __restrict__ d1,
                         __nv_bfloat16* __restrict__ d2, __nv_bfloat16* __restrict__ d3) {
    int i = blockIdx.x * 256 + threadIdx.x;     // 0..32767
    int idx = i * 16;
    const float* src; __nv_bfloat16* dst; int off;
    if (idx < 196608)      { src = s0; dst = d0; off = idx; }
    else if (idx < 262144) { src = s1; dst = d1; off = idx - 196608; }
    else if (idx < 393216) { src = s2; dst = d2; off = idx - 262144; }
    else                   { src = s3; dst = d3; off = idx - 393216; }
    float4 v0 = *(const float4*)(src + off);
    float4 v1 = *(const float4*)(src + off + 4);
    float4 v2 = *(const float4*)(src + off + 8);
    float4 v3 = *(const float4*)(src + off + 12);
    uint4 o0, o1;
    o0.x = packbf(v0.x, v0.y); o0.y = packbf(v0.z, v0.w);
    o0.z = packbf(v1.x, v1.y); o0.w = packbf(v1.z, v1.w);
    o1.x = packbf(v2.x, v2.y); o1.y = packbf(v2.z, v2.w);
    o1.z = packbf(v3.x, v3.y); o1.w = packbf(v3.z, v3.w);
    *(uint4*)(dst + off)     = o0;
    *(uint4*)(dst + off + 8) = o1;
}

// ---------------------------------------------------------------------------
// LayerNorm -> bf16: one WARP per row (8 rows per 256-thread block)
// ---------------------------------------------------------------------------
__device__ __forceinline__ float warp_sum(float v) {
    #pragma unroll
    for (int o = 16; o > 0; o >>= 1) v += __shfl_xor_sync(0xffffffffu, v, o);
    return v;
}

__global__ __launch_bounds__(256) void ln_kernel(const float* __restrict__ x,
                                                 const float* __restrict__ g,
                                                 const float* __restrict__ b,
                                                 __nv_bfloat16* __restrict__ y) {
    int row  = blockIdx.x * 8 + (threadIdx.x >> 5);
    int lane = threadIdx.x & 31;
    const float* xr = x + (size_t)row * DD + lane * 8;

    float4 v0 = *(const float4*)(xr);
    float4 v1 = *(const float4*)(xr + 4);
    float d[8] = {v0.x, v0.y, v0.z, v0.w, v1.x, v1.y, v1.z, v1.w};

    float s = d[0]+d[1]+d[2]+d[3]+d[4]+d[5]+d[6]+d[7];
    float mean = warp_sum(s) * (1.0f / DD);

    float ss = 0.f;
    #pragma unroll
    for (int j = 0; j < 8; j++) { d[j] -= mean; ss += d[j] * d[j]; }
    float var = warp_sum(ss) * (1.0f / DD);
    float r = rsqrtf(var + EPS);

    float4 g0 = *(const float4*)(g + lane * 8);
    float4 g1 = *(const float4*)(g + lane * 8 + 4);
    float4 b0 = *(const float4*)(b + lane * 8);
    float4 b1 = *(const float4*)(b + lane * 8 + 4);
    float gg[8] = {g0.x, g0.y, g0.z, g0.w, g1.x, g1.y, g1.z, g1.w};
    float bb2[8] = {b0.x, b0.y, b0.z, b0.w, b1.x, b1.y, b1.z, b1.w};

    float o[8];
    #pragma unroll
    for (int j = 0; j < 8; j++) o[j] = d[j] * r * gg[j] + bb2[j];

    uint4 pk;
    pk.x = packbf(o[0], o[1]);
    pk.y = packbf(o[2], o[3]);
    pk.z = packbf(o[4], o[5]);
    pk.w = packbf(o[6], o[7]);
    *(uint4*)&y[(size_t)row * DD + lane * 8] = pk;
}

// ---------------------------------------------------------------------------
// mma helpers
// ---------------------------------------------------------------------------
__device__ __forceinline__ void ldmx4(uint32_t& r0, uint32_t& r1,
                                      uint32_t& r2, uint32_t& r3, uint32_t a) {
    asm volatile("ldmatrix.sync.aligned.m8n8.x4.shared.b16 {%0,%1,%2,%3}, [%4];\n"
                 : "=r"(r0), "=r"(r1), "=r"(r2), "=r"(r3) : "r"(a));
}
__device__ __forceinline__ void ldmx4t(uint32_t& r0, uint32_t& r1,
                                       uint32_t& r2, uint32_t& r3, uint32_t a) {
    asm volatile("ldmatrix.sync.aligned.m8n8.x4.trans.shared.b16 {%0,%1,%2,%3}, [%4];\n"
                 : "=r"(r0), "=r"(r1), "=r"(r2), "=r"(r3) : "r"(a));
}
__device__ __forceinline__ void mma16816(float* c, const uint32_t* a, const uint32_t* b) {
    asm volatile("mma.sync.aligned.m16n8k16.row.col.f32.bf16.bf16.f32 "
                 "{%0,%1,%2,%3}, {%4,%5,%6,%7}, {%8,%9}, {%0,%1,%2,%3};\n"
                 : "+f"(c[0]), "+f"(c[1]), "+f"(c[2]), "+f"(c[3])
                 : "r"(a[0]), "r"(a[1]), "r"(a[2]), "r"(a[3]),
                   "r"(b[0]), "r"(b[1]));
}
__device__ __forceinline__ void mma16816h(float* c, const uint32_t* a, const uint32_t* b) {
    asm volatile("mma.sync.aligned.m16n8k16.row.col.f32.f16.f16.f32 "
                 "{%0,%1,%2,%3}, {%4,%5,%6,%7}, {%8,%9}, {%0,%1,%2,%3};\n"
                 : "+f"(c[0]), "+f"(c[1]), "+f"(c[2]), "+f"(c[3])
                 : "r"(a[0]), "r"(a[1]), "r"(a[2]), "r"(a[3]),
                   "r"(b[0]), "r"(b[1]));
}

// ---------------------------------------------------------------------------
// bf16 tensor-core NT GEMM with cp.async double-buffered tiles:
// C[n,m] = sum_k A[n,k]*W[m,k] + bias[m] (+ extras)
// Tile: 128 tokens x 64 features, BK=32. 256 threads = 8 warps (4 x 2).
// MODE 1: fp32 out + residual
// MODE 2: silu -> bf16 out
// MODE 3: qkv scatter (Q bf16 pre-scaled by ATT_SC2, K bf16, V fp16)
// MODE 4: like 1, but A = split-K partial O (2 x fp32) combined inline w/ pl
// ---------------------------------------------------------------------------
template<int MODE>
__global__ __launch_bounds__(256) void gemm_bf(
        const __nv_bfloat16* __restrict__ A,
        const __nv_bfloat16* __restrict__ W,
        const float* __restrict__ bias,
        const float* __restrict__ res,
        float* __restrict__ C,
        __nv_bfloat16* __restrict__ Ob,
        __nv_bfloat16* __restrict__ Kb,
        __half* __restrict__ Vh,
        const float* __restrict__ pl,
        int M, int K) {
    __shared__ __nv_bfloat16 As[2][128 * PITCH];
    __shared__ __nv_bfloat16 Bs[2][64 * PITCH];

    int t = threadIdx.x, w = t >> 5, lane = t & 31;
    int wm = w >> 1;
    int wn = w & 1;
    int row0 = blockIdx.y * 128;
    int col0 = blockIdx.x * 64;

    uint32_t ab_[2] = { (uint32_t)__cvta_generic_to_shared(As[0]),
                        (uint32_t)__cvta_generic_to_shared(As[1]) };
    uint32_t bb_[2] = { (uint32_t)__cvta_generic_to_shared(Bs[0]),
                        (uint32_t)__cvta_generic_to_shared(Bs[1]) };

    // cp.async indices: A 2 per thread, B 1 per thread
    int ar = t >> 1, ac = (t & 1) * 2;
    int br = t >> 2, bc = t & 3;
    uint32_t soA0 = (uint32_t)(ar * PITCH + ac * 8) * 2;
    uint32_t soA1 = (uint32_t)(ar * PITCH + (ac + 1) * 8) * 2;
    uint32_t soB  = (uint32_t)(br * PITCH + bc * 8) * 2;
    const __nv_bfloat16* asrc = A + (size_t)(row0 + ar) * K;
    const __nv_bfloat16* bsrc = W + (size_t)(col0 + br) * K;

    // MODE 4: inline split-K combine loader state
    int ar4 = t >> 1, ac4 = (t & 1) * 16;        // row 0..127, col group 0/16
    int n4  = row0 + ar4;
    const float* po0 = reinterpret_cast<const float*>(A) + (size_t)n4 * DD;
    const float* po1 = po0 + (size_t)NTOK * DD;
    float4 ra[4], rb[4];
    float pl0 = 0.f, pl1 = 0.f;

    float c[2][4][4];
    #pragma unroll
    for (int i = 0; i < 2; i++)
        #pragma unroll
        for (int j = 0; j < 4; j++)
            #pragma unroll
            for (int k = 0; k < 4; k++) c[i][j][k] = 0.f;

    // prologue
    cpa16(bb_[0] + soB, bsrc + bc * 8);
    if (MODE != 4) {
        cpa16(ab_[0] + soA0, asrc + ac * 8);
        cpa16(ab_[0] + soA1, asrc + (ac + 1) * 8);
    }
    asm volatile("cp.async.commit_group;");

    if (MODE == 4) {
        // load + combine k-tile 0 (head 0) into As[0]
        const float* s0 = po0 + ac4;
        const float* s1 = po1 + ac4;
        #pragma unroll
        for (int i = 0; i < 4; i++) {
            ra[i] = *(const float4*)(s0 + i * 4);
            rb[i] = *(const float4*)(s1 + i * 4);
        }
        pl0 = pl[(size_t)n4 * HH + 0];
        pl1 = pl[(size_t)NTOK * HH + (size_t)n4 * HH + 0];
        float inv = 1.0f / (pl0 + pl1);
        uint4 o0, o1;
        o0.x = packbf((ra[0].x+rb[0].x)*inv, (ra[0].y+rb[0].y)*inv);
        o0.y = packbf((ra[0].z+rb[0].z)*inv, (ra[0].w+rb[0].w)*inv);
        o0.z = packbf((ra[1].x+rb[1].x)*inv, (ra[1].y+rb[1].y)*inv);
        o0.w = packbf((ra[1].z+rb[1].z)*inv, (ra[1].w+rb[1].w)*inv);
        o1.x = packbf((ra[2].x+rb[2].x)*inv, (ra[2].y+rb[2].y)*inv);
        o1.y = packbf((ra[2].z+rb[2].z)*inv, (ra[2].w+rb[2].w)*inv);
        o1.z = packbf((ra[3].x+rb[3].x)*inv, (ra[3].y+rb[3].y)*inv);
        o1.w = packbf((ra[3].z+rb[3].z)*inv, (ra[3].w+rb[3].w)*inv);
        *(uint4*)&As[0][ar4 * PITCH + ac4]     = o0;
        *(uint4*)&As[0][ar4 * PITCH + ac4 + 8] = o1;
    }

    int NK = K >> 5;
    for (int it = 0; it < NK; it++) {
        int cur = it & 1;
        int nb = cur ^ 1;
        if (it + 1 < NK) {
            int k0 = (it + 1) * 32;
            cpa16(bb_[nb] + soB, bsrc + k0 + bc * 8);
            if (MODE != 4) {
                cpa16(ab_[nb] + soA0, asrc + k0 + ac * 8);
                cpa16(ab_[nb] + soA1, asrc + k0 + (ac + 1) * 8);
            }
            asm volatile("cp.async.commit_group;");
            asm volatile("cp.async.wait_group 1;");
        } else {
            asm volatile("cp.async.wait_group 0;");
        }
        __syncthreads();

        // MODE 4: issue next A-tile loads now (overlap with mma below)
        if (MODE == 4 && it + 1 < NK) {
            const float* s0 = po0 + (it + 1) * 32 + ac4;
            const float* s1 = po1 + (it + 1) * 32 + ac4;
            #pragma unroll
            for (int i = 0; i < 4; i++) {
                ra[i] = *(const float4*)(s0 + i * 4);
                rb[i] = *(const float4*)(s1 + i * 4);
            }
            pl0 = pl[(size_t)n4 * HH + (it + 1)];
            pl1 = pl[(size_t)NTOK * HH + (size_t)n4 * HH + (it + 1)];
        }

        uint32_t abase = ab_[cur], bbase = bb_[cur];
        uint32_t bf[2][2][4];
        #pragma unroll
        for (int nt = 0; nt < 2; nt++) {
            int nrow = wn * 32 + nt * 16 + (lane & 7) + ((lane >> 4) << 3);
            #pragma unroll
            for (int ks = 0; ks < 2; ks++) {
                uint32_t ad = bbase + (uint32_t)(nrow * PITCH + ks * 16 + (lane & 8)) * 2;
                ldmx4(bf[nt][ks][0], bf[nt][ks][1], bf[nt][ks][2], bf[nt][ks][3], ad);
            }
        }
        #pragma unroll
        for (int mt = 0; mt < 2; mt++) {
            int arow = wm * 32 + mt * 16 + (lane & 15);
            #pragma unroll
            for (int ks = 0; ks < 2; ks++) {
                uint32_t af[4];
                uint32_t ad = abase + (uint32_t)(arow * PITCH + ks * 16 + ((lane >> 4) << 3)) * 2;
                ldmx4(af[0], af[1], af[2], af[3], ad);
                #pragma unroll
                for (int nt = 0; nt < 2; nt++) {
                    mma16816(c[mt][2 * nt],     af, &bf[nt][ks][0]);
                    mma16816(c[mt][2 * nt + 1], af, &bf[nt][ks][2]);
                }
            }
        }

        // MODE 4: combine + store next A tile into the other buffer
        if (MODE == 4 && it + 1 < NK) {
            float inv = 1.0f / (pl0 + pl1);
            uint4 o0, o1;
            o0.x = packbf((ra[0].x+rb[0].x)*inv, (ra[0].y+rb[0].y)*inv);
            o0.y = packbf((ra[0].z+rb[0].z)*inv, (ra[0].w+rb[0].w)*inv);
            o0.z = packbf((ra[1].x+rb[1].x)*inv, (ra[1].y+rb[1].y)*inv);
            o0.w = packbf((ra[1].z+rb[1].z)*inv, (ra[1].w+rb[1].w)*inv);
            o1.x = packbf((ra[2].x+rb[2].x)*inv, (ra[2].y+rb[2].y)*inv);
            o1.y = packbf((ra[2].z+rb[2].z)*inv, (ra[2].w+rb[2].w)*inv);
            o1.z = packbf((ra[3].x+rb[3].x)*inv, (ra[3].y+rb[3].y)*inv);
            o1.w = packbf((ra[3].z+rb[3].z)*inv, (ra[3].w+rb[3].w)*inv);
            *(uint4*)&As[nb][ar4 * PITCH + ac4]     = o0;
            *(uint4*)&As[nb][ar4 * PITCH + ac4 + 8] = o1;
        }
        __syncthreads();
    }

    #pragma unroll
    for (int mt = 0; mt < 2; mt++) {
        #pragma unroll
        for (int half = 0; half < 2; half++) {
            int row = row0 + wm * 32 + mt * 16 + (lane >> 2) + half * 8;
            #pragma unroll
            for (int n8 = 0; n8 < 4; n8++) {
                int col = col0 + wn * 32 + n8 * 8 + 2 * (lane & 3);
                float v0 = c[mt][n8][2 * half]     + bias[col];
                float v1 = c[mt][n8][2 * half + 1] + bias[col + 1];
                if (MODE == 1 || MODE == 4) {
                    const float2 r2 = *(const float2*)&res[(size_t)row * M + col];
                    float2 o; o.x = v0 + r2.x; o.y = v1 + r2.y;
                    *(float2*)&C[(size_t)row * M + col] = o;
                } else if (MODE == 2) {
                    v0 = v0 * (1.0f / (1.0f + __expf(-v0)));
                    v1 = v1 * (1.0f / (1.0f + __expf(-v1)));
                    *(__nv_bfloat162*)&Ob[(size_t)row * M + col] =
                        __floats2bfloat162_rn(v0, v1);
                } else {
                    int seg = col >> 8, rem = col & 255;
                    int h = rem >> 5, d = rem & 31;
                    int b = row >> 11, s = row & 2047;
                    size_t di = ((size_t)(b * HH + h) * SS + s) * DHH + d;
                    if (seg == 0) {
                        // Q: pre-scale by softmax scale * log2e
                        *(__nv_bfloat162*)&Ob[di] =
                            __floats2bfloat162_rn(v0 * ATT_SC2, v1 * ATT_SC2);
                    } else if (seg == 1) {
                        *(__nv_bfloat162*)&Kb[di] = __floats2bfloat162_rn(v0, v1);
                    } else {
                        *(__half2*)&Vh[di] = __floats2half2_rn(v0, v1);
                    }
                }
            }
        }
    }
}

// ---------------------------------------------------------------------------
// Split-K tensor-core flash attention.
// S-mma: bf16 (Q pre-scaled). P = ex2.f16x2 of scores. PV-mma: fp16.
// grid (BH=32, S/128=16, KSPLIT=2), block 128 (4 warps; warp owns 32 q rows).
// Writes UNNORMALIZED partial O (fp32) and partial l.
// ---------------------------------------------------------------------------
__global__ __launch_bounds__(128) void attn_mma(const __nv_bfloat16* __restrict__ Qb,
                                                const __nv_bfloat16* __restrict__ Kb,
                                                const __half* __restrict__ Vh,
                                                float* __restrict__ po,
                                                float* __restrict__ pl) {
    __shared__ __nv_bfloat16 Qs[128 * PITCH];
    __shared__ __nv_bfloat16 Ks[2][64 * PITCH];
    __shared__ __half        Vs[2][64 * PITCH];

    int bh = blockIdx.x;
    int qt = blockIdx.y;
    int z  = blockIdx.z;
    int t = threadIdx.x, w = t >> 5, lane = t & 31;

    const __nv_bfloat16* qsrc = Qb + ((size_t)bh * SS + qt * 128) * DHH;
    const __nv_bfloat16* ksrc = Kb + ((size_t)bh * SS + z * KSEG) * DHH;
    const __half*        vsrc = Vh + ((size_t)bh * SS + z * KSEG) * DHH;

    uint32_t qbase = (uint32_t)__cvta_generic_to_shared(Qs);
    uint32_t kb_[2] = { (uint32_t)__cvta_generic_to_shared(Ks[0]),
                        (uint32_t)__cvta_generic_to_shared(Ks[1]) };
    uint32_t vb_[2] = { (uint32_t)__cvta_generic_to_shared(Vs[0]),
                        (uint32_t)__cvta_generic_to_shared(Vs[1]) };

    #pragma unroll
    for (int i = t; i < 512; i += 128) {
        int r = i >> 2, s = i & 3;
        *(uint4*)&Qs[r * PITCH + s * 8] = *(const uint4*)&qsrc[r * 32 + s * 8];
    }

    int lr = t >> 2, ls = t & 3;
    uint32_t so0 = (uint32_t)(lr * PITCH + ls * 8) * 2;
    uint32_t so1 = (uint32_t)((lr + 32) * PITCH + ls * 8) * 2;

    cpa16(kb_[0] + so0, &ksrc[lr * 32 + ls * 8]);
    cpa16(kb_[0] + so1, &ksrc[(lr + 32) * 32 + ls * 8]);
    cpa16(vb_[0] + so0, &vsrc[lr * 32 + ls * 8]);
    cpa16(vb_[0] + so1, &vsrc[(lr + 32) * 32 + ls * 8]);
    asm volatile("cp.async.commit_group;");

    __syncthreads();   // Q ready

    uint32_t qa[2][2][4];
    #pragma unroll
    for (int mt = 0; mt < 2; mt++) {
        int row = w * 32 + mt * 16 + (lane & 15);
        #pragma unroll
        for (int ks = 0; ks < 2; ks++) {
            uint32_t a = qbase + (uint32_t)(row * PITCH + ks * 16 + ((lane >> 4) << 3)) * 2;
            ldmx4(qa[mt][ks][0], qa[mt][ks][1], qa[mt][ks][2], qa[mt][ks][3], a);
        }
    }

    float O[2][4][4];
    #pragma unroll
    for (int mt = 0; mt < 2; mt++)
        #pragma unroll
        for (int i = 0; i < 4; i++)
            #pragma unroll
            for (int j = 0; j < 4; j++) O[mt][i][j] = 0.f;
    float Oext[2][4] = {{0.f,0.f,0.f,0.f},{0.f,0.f,0.f,0.f}};
    const uint32_t onesh[2] = {0x3C003C00u, 0x3C003C00u};   // f16 1.0 x2

    const int NIT = KSEG / 64;   // 16
    for (int it = 0; it < NIT; it++) {
        int cur = it & 1;
        if (it + 1 < NIT) {
            int koff = (it + 1) * 64;
            int nb = cur ^ 1;
            cpa16(kb_[nb] + so0, &ksrc[(koff + lr) * 32 + ls * 8]);
            cpa16(kb_[nb] + so1, &ksrc[(koff + lr + 32) * 32 + ls * 8]);
            cpa16(vb_[nb] + so0, &vsrc[(koff + lr) * 32 + ls * 8]);
            cpa16(vb_[nb] + so1, &vsrc[(koff + lr + 32) * 32 + ls * 8]);
            asm volatile("cp.async.commit_group;");
            asm volatile("cp.async.wait_group 1;");
        } else {
            asm volatile("cp.async.wait_group 0;");
        }
        __syncthreads();

        uint32_t kba = kb_[cur], vba = vb_[cur];
        #pragma unroll
        for (int j = 0; j < 4; j++) {            // 16-key slabs
            uint32_t b0[4], b1[4];
            int nrow = j * 16 + (lane & 7) + ((lane >> 4) << 3);
            ldmx4(b0[0], b0[1], b0[2], b0[3],
                  kba + (uint32_t)(nrow * PITCH + (lane & 8)) * 2);
            ldmx4(b1[0], b1[1], b1[2], b1[3],
                  kba + (uint32_t)(nrow * PITCH + 16 + (lane & 8)) * 2);

            float c[2][2][4];
            #pragma unroll
            for (int mt = 0; mt < 2; mt++) {
                #pragma unroll
                for (int i = 0; i < 4; i++) { c[mt][0][i] = 0.f; c[mt][1][i] = 0.f; }
                mma16816(c[mt][0], qa[mt][0], &b0[0]);
                mma16816(c[mt][0], qa[mt][1], &b1[0]);
                mma16816(c[mt][1], qa[mt][0], &b0[2]);
                mma16816(c[mt][1], qa[mt][1], &b1[2]);
            }

            // P = 2^score (scores pre-scaled via Q); one MUFU per 2 scores
            uint32_t pa[2][4];
            #pragma unroll
            for (int mt = 0; mt < 2; mt++) {
                pa[mt][0] = exp2h2(c[mt][0][0], c[mt][0][1]);
                pa[mt][1] = exp2h2(c[mt][0][2], c[mt][0][3]);
                pa[mt][2] = exp2h2(c[mt][1][0], c[mt][1][1]);
                pa[mt][3] = exp2h2(c[mt][1][2], c[mt][1][3]);
                mma16816h(Oext[mt], pa[mt], onesh);
            }

            int vrow = j * 16 + (lane & 15);
            uint32_t v0[4], v1[4];
            ldmx4t(v0[0], v0[1], v0[2], v0[3],
                   vba + (uint32_t)(vrow * PITCH + ((lane >> 4) << 3)) * 2);
            ldmx4t(v1[0], v1[1], v1[2], v1[3],
                   vba + (uint32_t)(vrow * PITCH + 16 + ((lane >> 4) << 3)) * 2);

            #pragma unroll
            for (int mt = 0; mt < 2; mt++) {
                mma16816h(O[mt][0], pa[mt], &v0[0]);
                mma16816h(O[mt][1], pa[mt], &v0[2]);
                mma16816h(O[mt][2], pa[mt], &v1[0]);
                mma16816h(O[mt][3], pa[mt], &v1[2]);
            }
        }
        __syncthreads();
    }

    int b = bh >> 3, h = bh & 7;
    float* poz = po + (size_t)z * NTOK * DD;
    float* plz = pl + (size_t)z * NTOK * HH;
    #pragma unroll
    for (int mt = 0; mt < 2; mt++) {
        int r0 = qt * 128 + w * 32 + mt * 16 + (lane >> 2);
        int n  = b * SS + r0;
        size_t base = (size_t)n * DD + h * DHH;
        if ((lane & 3) == 0) {
            plz[(size_t)n * HH + h]       = Oext[mt][0];
            plz[(size_t)(n + 8) * HH + h] = Oext[mt][2];
        }
        #pragma unroll
        for (int nt = 0; nt < 4; nt++) {
            int colo = nt * 8 + 2 * (lane & 3);
            float2 u0; u0.x = O[mt][nt][0]; u0.y = O[mt][nt][1];
            *(float2*)&poz[base + colo] = u0;
            float2 u1; u1.x = O[mt][nt][2]; u1.y = O[mt][nt][3];
            *(float2*)&poz[base + 8 * DD + colo] = u1;
        }
    }
}

// ---------------------------------------------------------------------------
// Launch
// ---------------------------------------------------------------------------
extern "C" void kernel_launch(void* const* d_in, const int* in_sizes, int n_in,
                              void* d_out, int out_size) {
    const float* x      = (const float*)d_in[0];
    const float* ln1_g  = (const float*)d_in[1];
    const float* ln1_b  = (const float*)d_in[2];
    const float* w_qkv  = (const float*)d_in[3];
    const float* b_qkv  = (const float*)d_in[4];
    const float* w_proj = (const float*)d_in[5];
    const float* b_proj = (const float*)d_in[6];
    const float* ln2_g  = (const float*)d_in[7];
    const float* ln2_b  = (const float*)d_in[8];
    const float* w1     = (const float*)d_in[9];
    const float* b1     = (const float*)d_in[10];
    const float* w2     = (const float*)d_in[11];
    const float* b2     = (const float*)d_in[12];
    float* out = (float*)d_out;

    __nv_bfloat16 *yb, *hb, *qb, *kb, *wqkvb, *wprojb, *w1b, *w2b;
    __half *vh;
    float *x1, *po, *pl;
    cudaGetSymbolAddress((void**)&yb,     g_yb);
    cudaGetSymbolAddress((void**)&x1,     g_x1);
    cudaGetSymbolAddress((void**)&hb,     g_hb);
    cudaGetSymbolAddress((void**)&qb,     g_qb);
    cudaGetSymbolAddress((void**)&kb,     g_kb);
    cudaGetSymbolAddress((void**)&vh,     g_vh);
    cudaGetSymbolAddress((void**)&wqkvb,  g_wqkvb);
    cudaGetSymbolAddress((void**)&wprojb, g_wprojb);
    cudaGetSymbolAddress((void**)&w1b,    g_w1b);
    cudaGetSymbolAddress((void**)&w2b,    g_w2b);
    cudaGetSymbolAddress((void**)&po,     g_po);
    cudaGetSymbolAddress((void**)&pl,     g_pl);

    // 0. all weights fp32 -> bf16, one launch
    f2bf_all<<<128, 256>>>(w_qkv, w_proj, w1, w2, wqkvb, wprojb, w1b, w2b);

    // 1. LN1 -> bf16
    ln_kernel<<<NTOK/8, 256>>>(x, ln1_g, ln1_b, yb);
    // 2. QKV GEMM -> Q bf16 (pre-scaled) / K bf16 / V fp16
    gemm_bf<3><<<dim3(768/64, NTOK/128), 256>>>(yb, wqkvb, b_qkv, nullptr, nullptr,
                                                qb, kb, vh, nullptr, 3*DD, DD);
    // 3. split-K attention -> partial O/l
    attn_mma<<<dim3(BB*HH, SS/128, KSPLIT), 128>>>(qb, kb, vh, po, pl);
    // 4. proj + residual with inline split-K combine -> x1 fp32
    gemm_bf<4><<<dim3(DD/64, NTOK/128), 256>>>((const __nv_bfloat16*)po, wprojb,
                                               b_proj, x, x1,
                                               nullptr, nullptr, nullptr, pl, DD, DD);
    // 5. LN2 -> bf16
    ln_kernel<<<NTOK/8, 256>>>(x1, ln2_g, ln2_b, yb);
    // 6. FFN1 + silu -> bf16 h
    gemm_bf<2><<<dim3(DFF/64, NTOK/128), 256>>>(yb, w1b, b1, nullptr, nullptr,
                                                hb, nullptr, nullptr, nullptr, DFF, DD);
    // 7. FFN2 + residual -> out fp32
    gemm_bf<1><<<dim3(DD/64, NTOK/128), 256>>>(hb, w2b, b2, x1, out,
                                               nullptr, nullptr, nullptr, nullptr, DD, DFF);
}